// round 3
// baseline (speedup 1.0000x reference)
#include <cuda_runtime.h>
#include <math.h>

#define BB 128
#define SS 512
#define EE 192
#define TT (BB*SS)      // 65536 tokens
#define QD 48
#define NH 3
#define HD 16

// ---------------- scratch (device globals; no allocation allowed) -------------
__device__ float g_qkv[2][TT][144];   // per branch: q[0:48] k[48:96] v[96:144]
__device__ float g_conv[TT][96];
__device__ float g_att[TT][96];       // acc heads 0:48, gyro heads 48:96 (pre-proj)
__device__ float g_x1[TT][EE];
__device__ float g_x1n[TT][EE];
__device__ float g_h[TT][384];

// ---------------- K1: LN1 + feature-conv + both QKV projections --------------
// one warp per token, 8 tokens / 256-thread block
#define SWS 289                        // padded stride for transposed qkv weights
#define K1_SMEM ((48*SWS + 8*192 + 288) * 4)

__global__ __launch_bounds__(256) void k1_ln_conv_qkv(
    const float* __restrict__ x,
    const float* __restrict__ ln1g, const float* __restrict__ ln1b,
    const float* __restrict__ accw, const float* __restrict__ accb,
    const float* __restrict__ gyrw, const float* __restrict__ gyrb,
    const float* __restrict__ convw)
{
    extern __shared__ float dsm[];
    float* swT   = dsm;                 // [48][SWS]: swT[i*SWS + j], j<144 acc, j>=144 gyro
    float* sx    = dsm + 48*SWS;        // [8][192]
    float* sbias = sx + 8*192;          // [288]

    int tid = threadIdx.x;
    // stage transposed weights: swT[i][row] = w[row][i]  (conflict-free: stride 289)
    for (int idx = tid; idx < 144*48; idx += 256) {
        int row = idx / 48, i = idx % 48;
        swT[i*SWS + row]        = accw[idx];
        swT[i*SWS + 144 + row]  = gyrw[idx];
    }
    for (int j = tid; j < 288; j += 256)
        sbias[j] = (j < 144) ? accb[j] : gyrb[j-144];

    int warp = tid >> 5, lane = tid & 31;
    int t = blockIdx.x * 8 + warp;

    // ---- LayerNorm 1 ----
    float v[6];
    float sum = 0.f, sq = 0.f;
    #pragma unroll
    for (int i = 0; i < 6; i++) {
        v[i] = x[(size_t)t*EE + lane + i*32];
        sum += v[i]; sq += v[i]*v[i];
    }
    #pragma unroll
    for (int o = 16; o > 0; o >>= 1) {
        sum += __shfl_xor_sync(0xffffffffu, sum, o);
        sq  += __shfl_xor_sync(0xffffffffu, sq,  o);
    }
    float mean = sum * (1.f/192.f);
    float var  = sq * (1.f/192.f) - mean*mean;
    float rstd = rsqrtf(var + 1e-6f);
    #pragma unroll
    for (int i = 0; i < 6; i++) {
        int f = lane + i*32;
        float xn = (v[i] - mean) * rstd * ln1g[f] + ln1b[f];
        sx[warp*192 + f] = xn;
    }
    __syncthreads();   // weights staged + sx visible

    // ---- depthwise conv along feature axis (channel = token % 4) ----
    {
        int c = t & 3;
        float cw[15];
        #pragma unroll
        for (int k = 0; k < 15; k++) cw[k] = convw[c*15 + k];
        const float* xw = sx + warp*192 + 48;   // the 96-wide slice
        #pragma unroll
        for (int r = 0; r < 3; r++) {
            int w = lane + r*32;
            float acc = 0.f;
            #pragma unroll
            for (int k = 0; k < 15; k++) {
                int idx = w + k - 7;
                if (idx >= 0 && idx < 96) acc += cw[k] * xw[idx];
            }
            g_conv[t][w] = acc;
        }
    }

    // ---- QKV for both branches: 288 outputs / token, 9 per lane ----
    {
        const float* xr = sx + warp*192;
        #pragma unroll
        for (int r = 0; r < 9; r++) {
            int j = lane + r*32;                 // 0..287
            int gy = (j >= 144);
            const float* xb = xr + (gy ? 96 : 0);
            float acc = sbias[j];
            #pragma unroll
            for (int i = 0; i < 48; i++)
                acc += swT[i*SWS + j] * xb[i];
            if (gy) g_qkv[1][t][j-144] = acc;
            else    g_qkv[0][t][j]     = acc;
        }
    }
}

// ---------------- K2: attention per (branch, batch, head) --------------------
#define K2_SMEM (2 * SS * HD * 4)      // 64 KB: Ks + Vs fp32

__global__ __launch_bounds__(256) void k2_attention()
{
    extern __shared__ float sm[];
    float* Ks = sm;
    float* Vs = sm + SS*HD;

    int br  = blockIdx.x / (BB*NH);
    int rem = blockIdx.x % (BB*NH);
    int b   = rem / NH;
    int h   = rem % NH;
    int tid = threadIdx.x;
    int tbase = b * SS;

    for (int idx = tid; idx < SS*HD; idx += 256) {
        int s = idx >> 4, d = idx & 15;
        Ks[idx] = g_qkv[br][tbase+s][48 + h*16 + d];
        Vs[idx] = g_qkv[br][tbase+s][96 + h*16 + d];
    }
    __syncthreads();

    const float4* K4 = (const float4*)Ks;
    const float4* V4 = (const float4*)Vs;

    for (int q = tid; q < SS; q += 256) {
        const float4* qp = (const float4*)&g_qkv[br][tbase+q][h*16];
        float4 q0 = qp[0], q1 = qp[1], q2 = qp[2], q3 = qp[3];

        // pass 1: row max
        float mx = -1e30f;
        #pragma unroll 4
        for (int k = 0; k < SS; k++) {
            float4 a = K4[k*4+0], bq = K4[k*4+1], c = K4[k*4+2], d = K4[k*4+3];
            float s = q0.x*a.x + q0.y*a.y + q0.z*a.z + q0.w*a.w
                    + q1.x*bq.x + q1.y*bq.y + q1.z*bq.z + q1.w*bq.w
                    + q2.x*c.x + q2.y*c.y + q2.z*c.z + q2.w*c.w
                    + q3.x*d.x + q3.y*d.y + q3.z*d.z + q3.w*d.w;
            mx = fmaxf(mx, s);
        }
        mx *= 0.25f;

        // pass 2: exp + P@V
        float l = 0.f;
        float4 acc0 = {0,0,0,0}, acc1 = {0,0,0,0}, acc2 = {0,0,0,0}, acc3 = {0,0,0,0};
        #pragma unroll 2
        for (int k = 0; k < SS; k++) {
            float4 a = K4[k*4+0], bq = K4[k*4+1], c = K4[k*4+2], d = K4[k*4+3];
            float s = q0.x*a.x + q0.y*a.y + q0.z*a.z + q0.w*a.w
                    + q1.x*bq.x + q1.y*bq.y + q1.z*bq.z + q1.w*bq.w
                    + q2.x*c.x + q2.y*c.y + q2.z*c.z + q2.w*c.w
                    + q3.x*d.x + q3.y*d.y + q3.z*d.z + q3.w*d.w;
            float p = __expf(s*0.25f - mx);
            l += p;
            float4 v0 = V4[k*4+0], v1 = V4[k*4+1], v2 = V4[k*4+2], v3 = V4[k*4+3];
            acc0.x += p*v0.x; acc0.y += p*v0.y; acc0.z += p*v0.z; acc0.w += p*v0.w;
            acc1.x += p*v1.x; acc1.y += p*v1.y; acc1.z += p*v1.z; acc1.w += p*v1.w;
            acc2.x += p*v2.x; acc2.y += p*v2.y; acc2.z += p*v2.z; acc2.w += p*v2.w;
            acc3.x += p*v3.x; acc3.y += p*v3.y; acc3.z += p*v3.z; acc3.w += p*v3.w;
        }
        float inv = 1.f / l;
        float* outp = &g_att[tbase+q][br*48 + h*16];
        outp[0]=acc0.x*inv; outp[1]=acc0.y*inv; outp[2]=acc0.z*inv; outp[3]=acc0.w*inv;
        outp[4]=acc1.x*inv; outp[5]=acc1.y*inv; outp[6]=acc1.z*inv; outp[7]=acc1.w*inv;
        outp[8]=acc2.x*inv; outp[9]=acc2.y*inv; outp[10]=acc2.z*inv; outp[11]=acc2.w*inv;
        outp[12]=acc3.x*inv; outp[13]=acc3.y*inv; outp[14]=acc3.z*inv; outp[15]=acc3.w*inv;
    }
}

// ---------------- K3a: output projections + concat + residual + LN2 ----------
__global__ __launch_bounds__(256) void k3a_proj_ln2(
    const float* __restrict__ x,
    const float* __restrict__ accwo, const float* __restrict__ accbo,
    const float* __restrict__ gyrwo, const float* __restrict__ gyrbo,
    const float* __restrict__ ln2g, const float* __restrict__ ln2b)
{
    __shared__ float woT[48*97];    // woT[i*97 + j], j<48 acc, j>=48 gyro
    __shared__ float satt[8][96];
    __shared__ float sproj[8][96];
    __shared__ float sb[96];

    int tid = threadIdx.x;
    for (int idx = tid; idx < 48*48; idx += 256) {
        int row = idx / 48, i = idx % 48;
        woT[i*97 + row]      = accwo[idx];
        woT[i*97 + 48 + row] = gyrwo[idx];
    }
    for (int j = tid; j < 96; j += 256)
        sb[j] = (j < 48) ? accbo[j] : gyrbo[j-48];

    int warp = tid >> 5, lane = tid & 31;
    int t = blockIdx.x * 8 + warp;

    #pragma unroll
    for (int r = 0; r < 3; r++)
        satt[warp][lane + r*32] = g_att[t][lane + r*32];
    __syncthreads();

    // projections: 96 outputs / token, 3 per lane
    #pragma unroll
    for (int r = 0; r < 3; r++) {
        int j = lane + r*32;
        const float* ab = &satt[warp][(j < 48) ? 0 : 48];
        float acc = sb[j];
        #pragma unroll
        for (int i = 0; i < 48; i++)
            acc += woT[i*97 + j] * ab[i];
        sproj[warp][j] = acc;
    }
    __syncwarp();

    // build x1 = concat + x, then LN2
    float xv[6];
    float sum = 0.f, sq = 0.f;
    #pragma unroll
    for (int i = 0; i < 6; i++) {
        int f = lane + i*32;
        float cv;
        if (f < 48)       cv = sproj[warp][f];
        else if (f < 144) cv = g_conv[t][f-48];
        else              cv = sproj[warp][48 + (f-144)];
        float x1 = cv + x[(size_t)t*EE + f];
        xv[i] = x1; sum += x1; sq += x1*x1;
    }
    #pragma unroll
    for (int o = 16; o > 0; o >>= 1) {
        sum += __shfl_xor_sync(0xffffffffu, sum, o);
        sq  += __shfl_xor_sync(0xffffffffu, sq,  o);
    }
    float mean = sum * (1.f/192.f);
    float var  = sq * (1.f/192.f) - mean*mean;
    float rstd = rsqrtf(var + 1e-6f);
    #pragma unroll
    for (int i = 0; i < 6; i++) {
        int f = lane + i*32;
        g_x1[t][f]  = xv[i];
        g_x1n[t][f] = (xv[i] - mean) * rstd * ln2g[f] + ln2b[f];
    }
}

// ---------------- tiled SGEMM: C = act(A @ B^T + bias) [+ Res] ----------------
// A [M,K] row-major, Bw [N,K] row-major. BM=128 BN=64 BK=16, 8x4 microtile.
__global__ __launch_bounds__(256) void gemm_bias_relu(
    const float* __restrict__ A, const float* __restrict__ Bw,
    const float* __restrict__ bias, const float* __restrict__ Res,
    float* __restrict__ C, int N, int K)
{
    __shared__ float As[16*129];
    __shared__ float Bs[16*65];

    int tid = threadIdx.x;
    int tx = tid & 15, ty = tid >> 4;
    int ms = blockIdx.x * 128;
    int ns = blockIdx.y * 64;

    float acc[8][4];
    #pragma unroll
    for (int i = 0; i < 8; i++)
        #pragma unroll
        for (int j = 0; j < 4; j++) acc[i][j] = 0.f;

    for (int k0 = 0; k0 < K; k0 += 16) {
        #pragma unroll
        for (int p = 0; p < 8; p++) {
            int idx = tid + p*256;
            int m = idx >> 4, kk = idx & 15;
            As[kk*129 + m] = A[(size_t)(ms+m)*K + k0 + kk];
        }
        #pragma unroll
        for (int p = 0; p < 4; p++) {
            int idx = tid + p*256;
            int n = idx >> 4, kk = idx & 15;
            Bs[kk*65 + n] = Bw[(size_t)(ns+n)*K + k0 + kk];
        }
        __syncthreads();
        #pragma unroll
        for (int kk = 0; kk < 16; kk++) {
            float a[8], b[4];
            #pragma unroll
            for (int i = 0; i < 8; i++) a[i] = As[kk*129 + ty*8 + i];
            #pragma unroll
            for (int j = 0; j < 4; j++) b[j] = Bs[kk*65 + tx*4 + j];
            #pragma unroll
            for (int i = 0; i < 8; i++)
                #pragma unroll
                for (int j = 0; j < 4; j++)
                    acc[i][j] += a[i]*b[j];
        }
        __syncthreads();
    }

    #pragma unroll
    for (int i = 0; i < 8; i++) {
        int m = ms + ty*8 + i;
        #pragma unroll
        for (int j = 0; j < 4; j++) {
            int n = ns + tx*4 + j;
            float vv = acc[i][j] + bias[n];
            vv = fmaxf(vv, 0.f);
            if (Res) vv += Res[(size_t)m*N + n];
            C[(size_t)m*N + n] = vv;
        }
    }
}

// ---------------- launcher ----------------------------------------------------
extern "C" void kernel_launch(void* const* d_in, const int* in_sizes, int n_in,
                              void* d_out, int out_size)
{
    const float* x     = (const float*)d_in[0];
    const float* ln1g  = (const float*)d_in[1];
    const float* ln1b  = (const float*)d_in[2];
    const float* accw  = (const float*)d_in[3];
    const float* accb  = (const float*)d_in[4];
    const float* accwo = (const float*)d_in[5];
    const float* accbo = (const float*)d_in[6];
    const float* gyrw  = (const float*)d_in[7];
    const float* gyrb  = (const float*)d_in[8];
    const float* gyrwo = (const float*)d_in[9];
    const float* gyrbo = (const float*)d_in[10];
    const float* convw = (const float*)d_in[11];
    const float* ln2g  = (const float*)d_in[12];
    const float* ln2b  = (const float*)d_in[13];
    const float* w1    = (const float*)d_in[14];
    const float* b1    = (const float*)d_in[15];
    const float* w2    = (const float*)d_in[16];
    const float* b2    = (const float*)d_in[17];
    float* out = (float*)d_out;

    cudaFuncSetAttribute(k1_ln_conv_qkv, cudaFuncAttributeMaxDynamicSharedMemorySize, K1_SMEM);
    cudaFuncSetAttribute(k2_attention,   cudaFuncAttributeMaxDynamicSharedMemorySize, K2_SMEM);

    void *p_x1, *p_x1n, *p_h;
    cudaGetSymbolAddress(&p_x1,  g_x1);
    cudaGetSymbolAddress(&p_x1n, g_x1n);
    cudaGetSymbolAddress(&p_h,   g_h);

    k1_ln_conv_qkv<<<TT/8, 256, K1_SMEM>>>(x, ln1g, ln1b, accw, accb, gyrw, gyrb, convw);
    k2_attention<<<2*BB*NH, 256, K2_SMEM>>>();
    k3a_proj_ln2<<<TT/8, 256>>>(x, accwo, accbo, gyrwo, gyrbo, ln2g, ln2b);

    // MLP: h = relu(x1n @ w1^T + b1);  out = x1 + relu(h @ w2^T + b2)
    gemm_bias_relu<<<dim3(TT/128, 384/64), 256>>>(
        (const float*)p_x1n, w1, b1, nullptr, (float*)p_h, 384, 192);
    gemm_bias_relu<<<dim3(TT/128, 192/64), 256>>>(
        (const float*)p_h, w2, b2, (const float*)p_x1, out, 192, 384);
}

// round 4
// speedup vs baseline: 1.5521x; 1.5521x over previous
#include <cuda_runtime.h>
#include <math.h>

#define BB 128
#define SS 512
#define EE 192
#define TT (BB*SS)      // 65536 tokens
#define QD 48
#define NH 3
#define HD 16

// ---------------- scratch (device globals; no allocation allowed) -------------
__device__ float g_qkv[2][TT][144];   // per branch: q[0:48] k[48:96] v[96:144]
__device__ float g_conv[TT][96];
__device__ float g_att[TT][96];       // acc heads 0:48, gyro heads 48:96 (pre-proj)
__device__ float g_x1[TT][EE];
__device__ float g_x1n[TT][EE];
__device__ float g_h[TT][384];

// ---------------- K1: LN1 + feature-conv + both QKV projections --------------
#define SWS 289
#define K1_SMEM ((48*SWS + 8*192 + 288) * 4)

__global__ __launch_bounds__(256) void k1_ln_conv_qkv(
    const float* __restrict__ x,
    const float* __restrict__ ln1g, const float* __restrict__ ln1b,
    const float* __restrict__ accw, const float* __restrict__ accb,
    const float* __restrict__ gyrw, const float* __restrict__ gyrb,
    const float* __restrict__ convw)
{
    extern __shared__ float dsm[];
    float* swT   = dsm;                 // [48][SWS]
    float* sx    = dsm + 48*SWS;        // [8][192]
    float* sbias = sx + 8*192;          // [288]

    int tid = threadIdx.x;
    for (int idx = tid; idx < 144*48; idx += 256) {
        int row = idx / 48, i = idx % 48;
        swT[i*SWS + row]        = accw[idx];
        swT[i*SWS + 144 + row]  = gyrw[idx];
    }
    for (int j = tid; j < 288; j += 256)
        sbias[j] = (j < 144) ? accb[j] : gyrb[j-144];

    int warp = tid >> 5, lane = tid & 31;
    int t = blockIdx.x * 8 + warp;

    float v[6];
    float sum = 0.f, sq = 0.f;
    #pragma unroll
    for (int i = 0; i < 6; i++) {
        v[i] = x[(size_t)t*EE + lane + i*32];
        sum += v[i]; sq += v[i]*v[i];
    }
    #pragma unroll
    for (int o = 16; o > 0; o >>= 1) {
        sum += __shfl_xor_sync(0xffffffffu, sum, o);
        sq  += __shfl_xor_sync(0xffffffffu, sq,  o);
    }
    float mean = sum * (1.f/192.f);
    float var  = sq * (1.f/192.f) - mean*mean;
    float rstd = rsqrtf(var + 1e-6f);
    #pragma unroll
    for (int i = 0; i < 6; i++) {
        int f = lane + i*32;
        float xn = (v[i] - mean) * rstd * ln1g[f] + ln1b[f];
        sx[warp*192 + f] = xn;
    }
    __syncthreads();

    // depthwise conv along feature axis (channel = token % 4)
    {
        int c = t & 3;
        float cw[15];
        #pragma unroll
        for (int k = 0; k < 15; k++) cw[k] = convw[c*15 + k];
        const float* xw = sx + warp*192 + 48;
        #pragma unroll
        for (int r = 0; r < 3; r++) {
            int w = lane + r*32;
            float acc = 0.f;
            #pragma unroll
            for (int k = 0; k < 15; k++) {
                int idx = w + k - 7;
                if (idx >= 0 && idx < 96) acc += cw[k] * xw[idx];
            }
            g_conv[t][w] = acc;
        }
    }

    // QKV (both branches): 288 outputs / token
    {
        const float* xr = sx + warp*192;
        #pragma unroll
        for (int r = 0; r < 9; r++) {
            int j = lane + r*32;
            int gy = (j >= 144);
            const float* xb = xr + (gy ? 96 : 0);
            float acc = sbias[j];
            #pragma unroll
            for (int i = 0; i < 48; i++)
                acc += swT[i*SWS + j] * xb[i];
            if (gy) g_qkv[1][t][j-144] = acc;
            else    g_qkv[0][t][j]     = acc;
        }
    }
}

// ---------------- K2: attention — single-pass softmax, 4 queries/thread ------
#define K2_SMEM (2 * SS * HD * 4)      // 64 KB

__global__ __launch_bounds__(128) void k2_attention()
{
    extern __shared__ float sm[];
    float* Ks = sm;
    float* Vs = sm + SS*HD;

    int br  = blockIdx.x / (BB*NH);
    int rem = blockIdx.x % (BB*NH);
    int b   = rem / NH;
    int h   = rem % NH;
    int tid = threadIdx.x;
    int tbase = b * SS;

    float4* Ks4 = (float4*)Ks;
    float4* Vs4 = (float4*)Vs;
    for (int i4 = tid; i4 < SS*4; i4 += 128) {
        int s = i4 >> 2, dq = i4 & 3;
        Ks4[i4] = *(const float4*)&g_qkv[br][tbase+s][48 + h*16 + dq*4];
        Vs4[i4] = *(const float4*)&g_qkv[br][tbase+s][96 + h*16 + dq*4];
    }
    __syncthreads();

    // 4 queries per thread: tid, tid+128, tid+256, tid+384
    float4 q[4][4];
    float4 acc[4][4];
    float  l[4];
    #pragma unroll
    for (int j = 0; j < 4; j++) {
        int qi = tid + j*128;
        const float4* qp = (const float4*)&g_qkv[br][tbase+qi][h*16];
        #pragma unroll
        for (int d = 0; d < 4; d++) {
            q[j][d] = qp[d];
            acc[j][d] = make_float4(0.f, 0.f, 0.f, 0.f);
        }
        l[j] = 0.f;
    }

    for (int k = 0; k < SS; k++) {
        float4 k0 = Ks4[k*4+0], k1 = Ks4[k*4+1], k2 = Ks4[k*4+2], k3 = Ks4[k*4+3];
        float4 v0 = Vs4[k*4+0], v1 = Vs4[k*4+1], v2 = Vs4[k*4+2], v3 = Vs4[k*4+3];
        #pragma unroll
        for (int j = 0; j < 4; j++) {
            float s = q[j][0].x*k0.x + q[j][0].y*k0.y + q[j][0].z*k0.z + q[j][0].w*k0.w
                    + q[j][1].x*k1.x + q[j][1].y*k1.y + q[j][1].z*k1.z + q[j][1].w*k1.w
                    + q[j][2].x*k2.x + q[j][2].y*k2.y + q[j][2].z*k2.z + q[j][2].w*k2.w
                    + q[j][3].x*k3.x + q[j][3].y*k3.y + q[j][3].z*k3.z + q[j][3].w*k3.w;
            float p = __expf(s * 0.25f);   // no max-subtraction: scores are O(1)
            l[j] += p;
            acc[j][0].x += p*v0.x; acc[j][0].y += p*v0.y; acc[j][0].z += p*v0.z; acc[j][0].w += p*v0.w;
            acc[j][1].x += p*v1.x; acc[j][1].y += p*v1.y; acc[j][1].z += p*v1.z; acc[j][1].w += p*v1.w;
            acc[j][2].x += p*v2.x; acc[j][2].y += p*v2.y; acc[j][2].z += p*v2.z; acc[j][2].w += p*v2.w;
            acc[j][3].x += p*v3.x; acc[j][3].y += p*v3.y; acc[j][3].z += p*v3.z; acc[j][3].w += p*v3.w;
        }
    }

    #pragma unroll
    for (int j = 0; j < 4; j++) {
        int qi = tid + j*128;
        float inv = 1.f / l[j];
        float* outp = &g_att[tbase+qi][br*48 + h*16];
        #pragma unroll
        for (int d = 0; d < 4; d++) {
            outp[d*4+0] = acc[j][d].x * inv;
            outp[d*4+1] = acc[j][d].y * inv;
            outp[d*4+2] = acc[j][d].z * inv;
            outp[d*4+3] = acc[j][d].w * inv;
        }
    }
}

// ---------------- K3a: output projections + concat + residual + LN2 ----------
__global__ __launch_bounds__(256) void k3a_proj_ln2(
    const float* __restrict__ x,
    const float* __restrict__ accwo, const float* __restrict__ accbo,
    const float* __restrict__ gyrwo, const float* __restrict__ gyrbo,
    const float* __restrict__ ln2g, const float* __restrict__ ln2b)
{
    __shared__ float woT[48*97];
    __shared__ float satt[8][96];
    __shared__ float sproj[8][96];
    __shared__ float sb[96];

    int tid = threadIdx.x;
    for (int idx = tid; idx < 48*48; idx += 256) {
        int row = idx / 48, i = idx % 48;
        woT[i*97 + row]      = accwo[idx];
        woT[i*97 + 48 + row] = gyrwo[idx];
    }
    for (int j = tid; j < 96; j += 256)
        sb[j] = (j < 48) ? accbo[j] : gyrbo[j-48];

    int warp = tid >> 5, lane = tid & 31;
    int t = blockIdx.x * 8 + warp;

    #pragma unroll
    for (int r = 0; r < 3; r++)
        satt[warp][lane + r*32] = g_att[t][lane + r*32];
    __syncthreads();

    #pragma unroll
    for (int r = 0; r < 3; r++) {
        int j = lane + r*32;
        const float* ab = &satt[warp][(j < 48) ? 0 : 48];
        float acc = sb[j];
        #pragma unroll
        for (int i = 0; i < 48; i++)
            acc += woT[i*97 + j] * ab[i];
        sproj[warp][j] = acc;
    }
    __syncwarp();

    float xv[6];
    float sum = 0.f, sq = 0.f;
    #pragma unroll
    for (int i = 0; i < 6; i++) {
        int f = lane + i*32;
        float cv;
        if (f < 48)       cv = sproj[warp][f];
        else if (f < 144) cv = g_conv[t][f-48];
        else              cv = sproj[warp][48 + (f-144)];
        float x1 = cv + x[(size_t)t*EE + f];
        xv[i] = x1; sum += x1; sq += x1*x1;
    }
    #pragma unroll
    for (int o = 16; o > 0; o >>= 1) {
        sum += __shfl_xor_sync(0xffffffffu, sum, o);
        sq  += __shfl_xor_sync(0xffffffffu, sq,  o);
    }
    float mean = sum * (1.f/192.f);
    float var  = sq * (1.f/192.f) - mean*mean;
    float rstd = rsqrtf(var + 1e-6f);
    #pragma unroll
    for (int i = 0; i < 6; i++) {
        int f = lane + i*32;
        g_x1[t][f]  = xv[i];
        g_x1n[t][f] = (xv[i] - mean) * rstd * ln2g[f] + ln2b[f];
    }
}

// ---------------- tf32 tensor-core GEMM: C = relu(A@Bw^T + bias) [+Res] ------
// A [M,K] row-major, Bw [N,K] row-major. BM=128 BN=64 BK=16.
// 8 warps: 4 (m) x 2 (n); each warp computes 32x32 via m16n8k8 tf32 mma.
// Smem tiles stored in fragment-permuted order -> conflict-free LDS128/LDS64.

__device__ __forceinline__ unsigned f2tf32(float v) {
    unsigned u;
    asm("cvt.rna.tf32.f32 %0, %1;" : "=r"(u) : "f"(v));
    return u;
}

__device__ __forceinline__ void mma_tf32(float4& c, const float4& a, const float2& b) {
    asm volatile(
        "mma.sync.aligned.m16n8k8.row.col.f32.tf32.tf32.f32 "
        "{%0,%1,%2,%3},{%4,%5,%6,%7},{%8,%9},{%0,%1,%2,%3};"
        : "+f"(c.x), "+f"(c.y), "+f"(c.z), "+f"(c.w)
        : "r"(__float_as_uint(a.x)), "r"(__float_as_uint(a.y)),
          "r"(__float_as_uint(a.z)), "r"(__float_as_uint(a.w)),
          "r"(__float_as_uint(b.x)), "r"(__float_as_uint(b.y)));
}

__global__ __launch_bounds__(256) void gemm_tf32(
    const float* __restrict__ A, const float* __restrict__ Bw,
    const float* __restrict__ bias, const float* __restrict__ Res,
    float* __restrict__ C, int N, int K)
{
    __shared__ float sA[128*16];   // permuted: [(mt*2+ktile)*32 + lane]*4 + reg
    __shared__ float sB[64*16];    // permuted: [(nt*2+ktile)*32 + lane]*2 + reg

    int tid  = threadIdx.x;
    int ms   = blockIdx.x * 128;
    int ns   = blockIdx.y * 64;
    int warp = tid >> 5, lane = tid & 31;
    int wm   = warp & 3;           // 0..3 -> m offset wm*32
    int wn   = warp >> 2;          // 0..1 -> n offset wn*32

    float4 acc[2][4];
    #pragma unroll
    for (int mi = 0; mi < 2; mi++)
        #pragma unroll
        for (int ni = 0; ni < 4; ni++)
            acc[mi][ni] = make_float4(0.f, 0.f, 0.f, 0.f);

    float4 ra[2], rb;

    // prefetch tile 0
    {
        #pragma unroll
        for (int p = 0; p < 2; p++) {
            int i4 = tid + p*256;
            int m = i4 >> 2, kq = i4 & 3;
            ra[p] = *(const float4*)&A[(size_t)(ms+m)*K + kq*4];
        }
        int n = tid >> 2, kq = tid & 3;
        rb = *(const float4*)&Bw[(size_t)(ns+n)*K + kq*4];
    }

    for (int k0 = 0; k0 < K; k0 += 16) {
        // store staged regs -> permuted smem (with tf32 rounding)
        #pragma unroll
        for (int p = 0; p < 2; p++) {
            int i4 = tid + p*256;
            int m = i4 >> 2, kq = i4 & 3;
            int mt = m >> 4, r = m & 15;
            int ktile = kq >> 1;
            int reg = ((kq & 1) << 1) | (r >> 3);
            int base = ((mt*2 + ktile)*32 + (r & 7)*4) * 4 + reg;
            float e[4] = {ra[p].x, ra[p].y, ra[p].z, ra[p].w};
            #pragma unroll
            for (int q = 0; q < 4; q++)
                sA[base + q*4] = __uint_as_float(f2tf32(e[q]));
        }
        {
            int n = tid >> 2, kq = tid & 3;
            int nt = n >> 3, c = n & 7;
            int ktile = kq >> 1;
            int reg = kq & 1;
            int base = ((nt*2 + ktile)*32 + c*4) * 2 + reg;
            float e[4] = {rb.x, rb.y, rb.z, rb.w};
            #pragma unroll
            for (int q = 0; q < 4; q++)
                sB[base + q*2] = __uint_as_float(f2tf32(e[q]));
        }
        __syncthreads();

        // prefetch next tile while computing
        bool last = (k0 + 16 >= K);
        if (!last) {
            #pragma unroll
            for (int p = 0; p < 2; p++) {
                int i4 = tid + p*256;
                int m = i4 >> 2, kq = i4 & 3;
                ra[p] = *(const float4*)&A[(size_t)(ms+m)*K + k0 + 16 + kq*4];
            }
            int n = tid >> 2, kq = tid & 3;
            rb = *(const float4*)&Bw[(size_t)(ns+n)*K + k0 + 16 + kq*4];
        }

        #pragma unroll
        for (int ktile = 0; ktile < 2; ktile++) {
            float4 av[2];
            float2 bv[4];
            #pragma unroll
            for (int mi = 0; mi < 2; mi++) {
                int mt = wm*2 + mi;
                av[mi] = *(const float4*)&sA[((mt*2 + ktile)*32 + lane)*4];
            }
            #pragma unroll
            for (int ni = 0; ni < 4; ni++) {
                int nt = wn*4 + ni;
                bv[ni] = *(const float2*)&sB[((nt*2 + ktile)*32 + lane)*2];
            }
            #pragma unroll
            for (int mi = 0; mi < 2; mi++)
                #pragma unroll
                for (int ni = 0; ni < 4; ni++)
                    mma_tf32(acc[mi][ni], av[mi], bv[ni]);
        }
        __syncthreads();
    }

    // epilogue: bias + relu (+Res)
    #pragma unroll
    for (int mi = 0; mi < 2; mi++) {
        #pragma unroll
        for (int ni = 0; ni < 4; ni++) {
            int m0 = ms + wm*32 + mi*16 + (lane >> 2);
            int n  = ns + wn*32 + ni*8 + (lane & 3)*2;
            float b0 = bias[n], b1 = bias[n+1];
            {
                float2 v;
                v.x = fmaxf(acc[mi][ni].x + b0, 0.f);
                v.y = fmaxf(acc[mi][ni].y + b1, 0.f);
                if (Res) { v.x += Res[(size_t)m0*N + n]; v.y += Res[(size_t)m0*N + n + 1]; }
                *(float2*)&C[(size_t)m0*N + n] = v;
            }
            {
                int m1 = m0 + 8;
                float2 v;
                v.x = fmaxf(acc[mi][ni].z + b0, 0.f);
                v.y = fmaxf(acc[mi][ni].w + b1, 0.f);
                if (Res) { v.x += Res[(size_t)m1*N + n]; v.y += Res[(size_t)m1*N + n + 1]; }
                *(float2*)&C[(size_t)m1*N + n] = v;
            }
        }
    }
}

// ---------------- launcher ----------------------------------------------------
extern "C" void kernel_launch(void* const* d_in, const int* in_sizes, int n_in,
                              void* d_out, int out_size)
{
    const float* x     = (const float*)d_in[0];
    const float* ln1g  = (const float*)d_in[1];
    const float* ln1b  = (const float*)d_in[2];
    const float* accw  = (const float*)d_in[3];
    const float* accb  = (const float*)d_in[4];
    const float* accwo = (const float*)d_in[5];
    const float* accbo = (const float*)d_in[6];
    const float* gyrw  = (const float*)d_in[7];
    const float* gyrb  = (const float*)d_in[8];
    const float* gyrwo = (const float*)d_in[9];
    const float* gyrbo = (const float*)d_in[10];
    const float* convw = (const float*)d_in[11];
    const float* ln2g  = (const float*)d_in[12];
    const float* ln2b  = (const float*)d_in[13];
    const float* w1    = (const float*)d_in[14];
    const float* b1    = (const float*)d_in[15];
    const float* w2    = (const float*)d_in[16];
    const float* b2    = (const float*)d_in[17];
    float* out = (float*)d_out;

    cudaFuncSetAttribute(k1_ln_conv_qkv, cudaFuncAttributeMaxDynamicSharedMemorySize, K1_SMEM);
    cudaFuncSetAttribute(k2_attention,   cudaFuncAttributeMaxDynamicSharedMemorySize, K2_SMEM);

    void *p_x1, *p_x1n, *p_h;
    cudaGetSymbolAddress(&p_x1,  g_x1);
    cudaGetSymbolAddress(&p_x1n, g_x1n);
    cudaGetSymbolAddress(&p_h,   g_h);

    k1_ln_conv_qkv<<<TT/8, 256, K1_SMEM>>>(x, ln1g, ln1b, accw, accb, gyrw, gyrb, convw);
    k2_attention<<<2*BB*NH, 128, K2_SMEM>>>();
    k3a_proj_ln2<<<TT/8, 256>>>(x, accwo, accbo, gyrwo, gyrbo, ln2g, ln2b);

    // MLP: h = relu(x1n @ w1^T + b1);  out = x1 + relu(h @ w2^T + b2)
    gemm_tf32<<<dim3(TT/128, 384/64), 256>>>(
        (const float*)p_x1n, w1, b1, nullptr, (float*)p_h, 384, 192);
    gemm_tf32<<<dim3(TT/128, 192/64), 256>>>(
        (const float*)p_h, w2, b2, (const float*)p_x1, out, 192, 384);
}

// round 5
// speedup vs baseline: 1.6673x; 1.0742x over previous
#include <cuda_runtime.h>
#include <math.h>

#define BB 128
#define SS 512
#define EE 192
#define TT (BB*SS)      // 65536 tokens
#define QD 48
#define NH 3
#define HD 16

// ---------------- scratch (device globals; no allocation allowed) -------------
__device__ float g_qkv[2][TT][144];   // per branch: q[0:48] k[48:96] v[96:144]
__device__ float g_conv[TT][96];
__device__ float g_att[TT][96];       // acc heads 0:48, gyro heads 48:96 (pre-proj)
__device__ float g_x1[TT][EE];
__device__ float g_x1n[TT][EE];
__device__ float g_h[TT][384];

__device__ __forceinline__ unsigned f2tf32(float v) {
    unsigned u;
    asm("cvt.rna.tf32.f32 %0, %1;" : "=r"(u) : "f"(v));
    return u;
}
__device__ __forceinline__ float tf32f(float v) { return __uint_as_float(f2tf32(v)); }

__device__ __forceinline__ void mma_tf32(float4& c, const float4& a, const float2& b) {
    asm volatile(
        "mma.sync.aligned.m16n8k8.row.col.f32.tf32.tf32.f32 "
        "{%0,%1,%2,%3},{%4,%5,%6,%7},{%8,%9},{%0,%1,%2,%3};"
        : "+f"(c.x), "+f"(c.y), "+f"(c.z), "+f"(c.w)
        : "r"(__float_as_uint(a.x)), "r"(__float_as_uint(a.y)),
          "r"(__float_as_uint(a.z)), "r"(__float_as_uint(a.w)),
          "r"(__float_as_uint(b.x)), "r"(__float_as_uint(b.y)));
}

// ---------------- K1: LN1 + feature-conv + both QKV projections --------------
#define SWS 289
#define K1_SMEM ((48*SWS + 8*192 + 288) * 4)

__global__ __launch_bounds__(256) void k1_ln_conv_qkv(
    const float* __restrict__ x,
    const float* __restrict__ ln1g, const float* __restrict__ ln1b,
    const float* __restrict__ accw, const float* __restrict__ accb,
    const float* __restrict__ gyrw, const float* __restrict__ gyrb,
    const float* __restrict__ convw)
{
    extern __shared__ float dsm[];
    float* swT   = dsm;
    float* sx    = dsm + 48*SWS;
    float* sbias = sx + 8*192;

    int tid = threadIdx.x;
    for (int idx = tid; idx < 144*48; idx += 256) {
        int row = idx / 48, i = idx % 48;
        swT[i*SWS + row]        = accw[idx];
        swT[i*SWS + 144 + row]  = gyrw[idx];
    }
    for (int j = tid; j < 288; j += 256)
        sbias[j] = (j < 144) ? accb[j] : gyrb[j-144];

    int warp = tid >> 5, lane = tid & 31;
    int t = blockIdx.x * 8 + warp;

    float v[6];
    float sum = 0.f, sq = 0.f;
    #pragma unroll
    for (int i = 0; i < 6; i++) {
        v[i] = x[(size_t)t*EE + lane + i*32];
        sum += v[i]; sq += v[i]*v[i];
    }
    #pragma unroll
    for (int o = 16; o > 0; o >>= 1) {
        sum += __shfl_xor_sync(0xffffffffu, sum, o);
        sq  += __shfl_xor_sync(0xffffffffu, sq,  o);
    }
    float mean = sum * (1.f/192.f);
    float var  = sq * (1.f/192.f) - mean*mean;
    float rstd = rsqrtf(var + 1e-6f);
    #pragma unroll
    for (int i = 0; i < 6; i++) {
        int f = lane + i*32;
        float xn = (v[i] - mean) * rstd * ln1g[f] + ln1b[f];
        sx[warp*192 + f] = xn;
    }
    __syncthreads();

    {
        int c = t & 3;
        float cw[15];
        #pragma unroll
        for (int k = 0; k < 15; k++) cw[k] = convw[c*15 + k];
        const float* xw = sx + warp*192 + 48;
        #pragma unroll
        for (int r = 0; r < 3; r++) {
            int w = lane + r*32;
            float acc = 0.f;
            #pragma unroll
            for (int k = 0; k < 15; k++) {
                int idx = w + k - 7;
                if (idx >= 0 && idx < 96) acc += cw[k] * xw[idx];
            }
            g_conv[t][w] = acc;
        }
    }

    {
        const float* xr = sx + warp*192;
        #pragma unroll
        for (int r = 0; r < 9; r++) {
            int j = lane + r*32;
            int gy = (j >= 144);
            const float* xb = xr + (gy ? 96 : 0);
            float acc = sbias[j];
            #pragma unroll
            for (int i = 0; i < 48; i++)
                acc += swT[i*SWS + j] * xb[i];
            if (gy) g_qkv[1][t][j-144] = acc;
            else    g_qkv[0][t][j]     = acc;
        }
    }
}

// ---------------- K2: tensor-core attention (tf32 mma, single-pass) ----------
// grid: ((br*BB + b)*NH + h)*4 + qb ; 256 threads (8 warps, 16 queries each)
// smem: sK (32KB, QK B-frags), sV (32KB, PV B-frags), sP (per-warp 16x68)
#define K2_SMEM ((8192 + 8192 + 8*16*68) * 4)

__global__ __launch_bounds__(256) void k2_attn_mma()
{
    extern __shared__ float sm[];
    float* sK = sm;            // [(keytile8*2 + hdtile)*32 + lane]*2 + reg
    float* sV = sm + 8192;     // [(keytile8*2 + hdtile)*32 + lane]*2 + reg
    float* sP = sm + 16384;    // per warp [16][68]

    int tid = threadIdx.x;
    int qb   = blockIdx.x & 3;
    int rest = blockIdx.x >> 2;
    int h  = rest % NH;  rest /= NH;
    int b  = rest % BB;
    int br = rest / BB;
    int tbase = b * SS;

    // stage K,V in mma-B fragment layouts (tf32)
    for (int idx = tid; idx < SS*HD; idx += 256) {
        int key = idx >> 4, d = idx & 15;
        float kv = g_qkv[br][tbase+key][48 + h*16 + d];
        float vv = g_qkv[br][tbase+key][96 + h*16 + d];
        // K as B operand of S=Q@K^T: n=key, k=d
        int laneK = (key & 7)*4 + (d & 3);
        sK[(((key>>3)*2 + (d>>3))*32 + laneK)*2 + ((d>>2)&1)] = tf32f(kv);
        // V as B operand of O=P@V: k=key, n=d
        int laneV = (d & 7)*4 + (key & 3);
        sV[(((key>>3)*2 + (d>>3))*32 + laneV)*2 + ((key>>2)&1)] = tf32f(vv);
    }

    int wq = tid >> 5, lane = tid & 31;
    int g = lane >> 2, t4 = lane & 3;
    int q0 = tbase + qb*128 + wq*16;

    // Q fragments (scale 0.25 folded in)
    float4 qa[2];
    {
        const float* qr0 = &g_qkv[br][q0+g][h*16];
        const float* qr1 = &g_qkv[br][q0+g+8][h*16];
        #pragma unroll
        for (int kt = 0; kt < 2; kt++) {
            qa[kt].x = tf32f(qr0[kt*8 + t4]     * 0.25f);
            qa[kt].y = tf32f(qr1[kt*8 + t4]     * 0.25f);
            qa[kt].z = tf32f(qr0[kt*8 + t4 + 4] * 0.25f);
            qa[kt].w = tf32f(qr1[kt*8 + t4 + 4] * 0.25f);
        }
    }
    __syncthreads();

    float4 oacc[2];
    oacc[0] = make_float4(0.f,0.f,0.f,0.f);
    oacc[1] = make_float4(0.f,0.f,0.f,0.f);
    float l0 = 0.f, l1 = 0.f;
    float* sPw = sP + wq*16*68;

    for (int kb = 0; kb < 8; kb++) {         // keyblocks of 64
        float4 sacc[8];
        #pragma unroll
        for (int ni = 0; ni < 8; ni++) sacc[ni] = make_float4(0.f,0.f,0.f,0.f);

        #pragma unroll
        for (int ni = 0; ni < 8; ni++) {
            int nt = kb*8 + ni;
            mma_tf32(sacc[ni], qa[0], *(const float2*)&sK[((nt*2+0)*32 + lane)*2]);
            mma_tf32(sacc[ni], qa[1], *(const float2*)&sK[((nt*2+1)*32 + lane)*2]);
        }
        #pragma unroll
        for (int ni = 0; ni < 8; ni++) {
            float px = __expf(sacc[ni].x), py = __expf(sacc[ni].y);
            float pz = __expf(sacc[ni].z), pw = __expf(sacc[ni].w);
            l0 += px + py; l1 += pz + pw;
            float2 hi = make_float2(tf32f(px), tf32f(py));
            float2 lo = make_float2(tf32f(pz), tf32f(pw));
            *(float2*)&sPw[ g   *68 + ni*8 + 2*t4] = hi;
            *(float2*)&sPw[(g+8)*68 + ni*8 + 2*t4] = lo;
        }
        __syncwarp();
        #pragma unroll
        for (int kt2 = 0; kt2 < 8; kt2++) {
            float4 af;
            af.x = sPw[ g   *68 + kt2*8 + t4];
            af.y = sPw[(g+8)*68 + kt2*8 + t4];
            af.z = sPw[ g   *68 + kt2*8 + t4 + 4];
            af.w = sPw[(g+8)*68 + kt2*8 + t4 + 4];
            int ktg = kb*8 + kt2;
            mma_tf32(oacc[0], af, *(const float2*)&sV[((ktg*2+0)*32 + lane)*2]);
            mma_tf32(oacc[1], af, *(const float2*)&sV[((ktg*2+1)*32 + lane)*2]);
        }
        __syncwarp();
    }

    // reduce row-sums across the quad (lanes sharing g)
    l0 += __shfl_xor_sync(0xffffffffu, l0, 1);
    l0 += __shfl_xor_sync(0xffffffffu, l0, 2);
    l1 += __shfl_xor_sync(0xffffffffu, l1, 1);
    l1 += __shfl_xor_sync(0xffffffffu, l1, 2);
    float i0 = 1.f / l0, i1 = 1.f / l1;

    #pragma unroll
    for (int nt = 0; nt < 2; nt++) {
        int col = br*48 + h*16 + nt*8 + 2*t4;
        *(float2*)&g_att[q0+g  ][col] = make_float2(oacc[nt].x*i0, oacc[nt].y*i0);
        *(float2*)&g_att[q0+g+8][col] = make_float2(oacc[nt].z*i1, oacc[nt].w*i1);
    }
}

// ---------------- K3a: output projections + concat + residual + LN2 ----------
__global__ __launch_bounds__(256) void k3a_proj_ln2(
    const float* __restrict__ x,
    const float* __restrict__ accwo, const float* __restrict__ accbo,
    const float* __restrict__ gyrwo, const float* __restrict__ gyrbo,
    const float* __restrict__ ln2g, const float* __restrict__ ln2b)
{
    __shared__ float woT[48*97];
    __shared__ float satt[8][96];
    __shared__ float sproj[8][96];
    __shared__ float sb[96];

    int tid = threadIdx.x;
    for (int idx = tid; idx < 48*48; idx += 256) {
        int row = idx / 48, i = idx % 48;
        woT[i*97 + row]      = accwo[idx];
        woT[i*97 + 48 + row] = gyrwo[idx];
    }
    for (int j = tid; j < 96; j += 256)
        sb[j] = (j < 48) ? accbo[j] : gyrbo[j-48];

    int warp = tid >> 5, lane = tid & 31;
    int t = blockIdx.x * 8 + warp;

    #pragma unroll
    for (int r = 0; r < 3; r++)
        satt[warp][lane + r*32] = g_att[t][lane + r*32];
    __syncthreads();

    #pragma unroll
    for (int r = 0; r < 3; r++) {
        int j = lane + r*32;
        const float* ab = &satt[warp][(j < 48) ? 0 : 48];
        float acc = sb[j];
        #pragma unroll
        for (int i = 0; i < 48; i++)
            acc += woT[i*97 + j] * ab[i];
        sproj[warp][j] = acc;
    }
    __syncwarp();

    float xv[6];
    float sum = 0.f, sq = 0.f;
    #pragma unroll
    for (int i = 0; i < 6; i++) {
        int f = lane + i*32;
        float cv;
        if (f < 48)       cv = sproj[warp][f];
        else if (f < 144) cv = g_conv[t][f-48];
        else              cv = sproj[warp][48 + (f-144)];
        float x1 = cv + x[(size_t)t*EE + f];
        xv[i] = x1; sum += x1; sq += x1*x1;
    }
    #pragma unroll
    for (int o = 16; o > 0; o >>= 1) {
        sum += __shfl_xor_sync(0xffffffffu, sum, o);
        sq  += __shfl_xor_sync(0xffffffffu, sq,  o);
    }
    float mean = sum * (1.f/192.f);
    float var  = sq * (1.f/192.f) - mean*mean;
    float rstd = rsqrtf(var + 1e-6f);
    #pragma unroll
    for (int i = 0; i < 6; i++) {
        int f = lane + i*32;
        g_x1[t][f]  = xv[i];
        g_x1n[t][f] = (xv[i] - mean) * rstd * ln2g[f] + ln2b[f];
    }
}

// ---------------- tf32 GEMM v2: weight-resident smem, A via direct LDG -------
// C = relu(A@Bw^T + bias) [+Res]. A [M,K] row-major, Bw [N,K] row-major.
// BM=128 BN=64; K processed in resident chunks of 192 (K % 192 == 0).
// No mainloop __syncthreads.
__global__ __launch_bounds__(256) void gemm_tf32_v2(
    const float* __restrict__ A, const float* __restrict__ Bw,
    const float* __restrict__ bias, const float* __restrict__ Res,
    float* __restrict__ C, int N, int K)
{
    __shared__ float sB[64*192];   // 48KB, fragment-permuted

    int tid  = threadIdx.x;
    int ms   = blockIdx.x * 128;
    int ns   = blockIdx.y * 64;
    int warp = tid >> 5, lane = tid & 31;
    int wm   = warp & 3;
    int wn   = warp >> 2;
    int g = lane >> 2, t4 = lane & 3;

    float4 acc[2][4];
    #pragma unroll
    for (int mi = 0; mi < 2; mi++)
        #pragma unroll
        for (int ni = 0; ni < 4; ni++)
            acc[mi][ni] = make_float4(0.f,0.f,0.f,0.f);

    const float *r0[2], *r1[2];
    #pragma unroll
    for (int mi = 0; mi < 2; mi++) {
        int mb = ms + wm*32 + mi*16;
        r0[mi] = A + (size_t)(mb+g)*K   + t4;
        r1[mi] = A + (size_t)(mb+g+8)*K + t4;
    }

    for (int kc = 0; kc < K; kc += 192) {
        __syncthreads();
        // stage B chunk once (fragment layout, tf32)
        for (int i4 = tid; i4 < 64*48; i4 += 256) {
            int n = i4 / 48, kq = i4 % 48;
            float4 e = *(const float4*)&Bw[(size_t)(ns+n)*K + kc + kq*4];
            float ev[4] = {e.x, e.y, e.z, e.w};
            int nt = n >> 3, cb = (n & 7)*4;
            #pragma unroll
            for (int q = 0; q < 4; q++) {
                int k = kq*4 + q;
                sB[(((nt*24 + (k>>3))*32 + cb + (k&3)))*2 + ((k>>2)&1)] = tf32f(ev[q]);
            }
        }
        __syncthreads();

        #pragma unroll 4
        for (int kt = 0; kt < 24; kt++) {
            int kk = kc + kt*8;
            float4 av[2];
            #pragma unroll
            for (int mi = 0; mi < 2; mi++) {
                av[mi].x = tf32f(r0[mi][kk]);
                av[mi].y = tf32f(r1[mi][kk]);
                av[mi].z = tf32f(r0[mi][kk+4]);
                av[mi].w = tf32f(r1[mi][kk+4]);
            }
            #pragma unroll
            for (int ni = 0; ni < 4; ni++) {
                float2 bf = *(const float2*)&sB[(((wn*4+ni)*24 + kt)*32 + lane)*2];
                mma_tf32(acc[0][ni], av[0], bf);
                mma_tf32(acc[1][ni], av[1], bf);
            }
        }
    }

    // epilogue: bias + relu (+Res)
    #pragma unroll
    for (int mi = 0; mi < 2; mi++) {
        #pragma unroll
        for (int ni = 0; ni < 4; ni++) {
            int m0 = ms + wm*32 + mi*16 + g;
            int n  = ns + wn*32 + ni*8 + t4*2;
            float b0 = bias[n], b1 = bias[n+1];
            {
                float2 v;
                v.x = fmaxf(acc[mi][ni].x + b0, 0.f);
                v.y = fmaxf(acc[mi][ni].y + b1, 0.f);
                if (Res) { v.x += Res[(size_t)m0*N + n]; v.y += Res[(size_t)m0*N + n + 1]; }
                *(float2*)&C[(size_t)m0*N + n] = v;
            }
            {
                int m1 = m0 + 8;
                float2 v;
                v.x = fmaxf(acc[mi][ni].z + b0, 0.f);
                v.y = fmaxf(acc[mi][ni].w + b1, 0.f);
                if (Res) { v.x += Res[(size_t)m1*N + n]; v.y += Res[(size_t)m1*N + n + 1]; }
                *(float2*)&C[(size_t)m1*N + n] = v;
            }
        }
    }
}

// ---------------- launcher ----------------------------------------------------
extern "C" void kernel_launch(void* const* d_in, const int* in_sizes, int n_in,
                              void* d_out, int out_size)
{
    const float* x     = (const float*)d_in[0];
    const float* ln1g  = (const float*)d_in[1];
    const float* ln1b  = (const float*)d_in[2];
    const float* accw  = (const float*)d_in[3];
    const float* accb  = (const float*)d_in[4];
    const float* accwo = (const float*)d_in[5];
    const float* accbo = (const float*)d_in[6];
    const float* gyrw  = (const float*)d_in[7];
    const float* gyrb  = (const float*)d_in[8];
    const float* gyrwo = (const float*)d_in[9];
    const float* gyrbo = (const float*)d_in[10];
    const float* convw = (const float*)d_in[11];
    const float* ln2g  = (const float*)d_in[12];
    const float* ln2b  = (const float*)d_in[13];
    const float* w1    = (const float*)d_in[14];
    const float* b1    = (const float*)d_in[15];
    const float* w2    = (const float*)d_in[16];
    const float* b2    = (const float*)d_in[17];
    float* out = (float*)d_out;

    cudaFuncSetAttribute(k1_ln_conv_qkv, cudaFuncAttributeMaxDynamicSharedMemorySize, K1_SMEM);
    cudaFuncSetAttribute(k2_attn_mma,    cudaFuncAttributeMaxDynamicSharedMemorySize, K2_SMEM);

    void *p_x1, *p_x1n, *p_h;
    cudaGetSymbolAddress(&p_x1,  g_x1);
    cudaGetSymbolAddress(&p_x1n, g_x1n);
    cudaGetSymbolAddress(&p_h,   g_h);

    k1_ln_conv_qkv<<<TT/8, 256, K1_SMEM>>>(x, ln1g, ln1b, accw, accb, gyrw, gyrb, convw);
    k2_attn_mma<<<2*BB*NH*4, 256, K2_SMEM>>>();
    k3a_proj_ln2<<<TT/8, 256>>>(x, accwo, accbo, gyrwo, gyrbo, ln2g, ln2b);

    // MLP: h = relu(x1n @ w1^T + b1);  out = x1 + relu(h @ w2^T + b2)
    gemm_tf32_v2<<<dim3(TT/128, 384/64), 256>>>(
        (const float*)p_x1n, w1, b1, nullptr, (float*)p_h, 384, 192);
    gemm_tf32_v2<<<dim3(TT/128, 192/64), 256>>>(
        (const float*)p_h, w2, b2, (const float*)p_x1, out, 192, 384);
}

// round 9
// speedup vs baseline: 2.4656x; 1.4788x over previous
#include <cuda_runtime.h>
#include <cstdint>
#include <math.h>

#define BB 128
#define SS 512
#define EE 192
#define TT (BB*SS)      // 65536 tokens
#define QD 48
#define NH 3
#define HD 16

// ---------------- scratch (device globals; no allocation allowed) -------------
__device__ float g_qkv[2][TT][144];   // per branch: q[0:48] k[48:96] v[96:144]
__device__ float g_conv[TT][96];
__device__ float g_att[TT][96];       // acc heads 0:48, gyro heads 48:96 (pre-proj)
__device__ float g_x1[TT][EE];
__device__ float g_x1n[TT][EE];
__device__ float g_h[TT][384];

__device__ __forceinline__ unsigned f2tf32(float v) {
    unsigned u;
    asm("cvt.rna.tf32.f32 %0, %1;" : "=r"(u) : "f"(v));
    return u;
}
__device__ __forceinline__ float tf32f(float v) { return __uint_as_float(f2tf32(v)); }

__device__ __forceinline__ void mma_tf32(float4& c, const float4& a, const float2& b) {
    asm volatile(
        "mma.sync.aligned.m16n8k8.row.col.f32.tf32.tf32.f32 "
        "{%0,%1,%2,%3},{%4,%5,%6,%7},{%8,%9},{%0,%1,%2,%3};"
        : "+f"(c.x), "+f"(c.y), "+f"(c.z), "+f"(c.w)
        : "r"(__float_as_uint(a.x)), "r"(__float_as_uint(a.y)),
          "r"(__float_as_uint(a.z)), "r"(__float_as_uint(a.w)),
          "r"(__float_as_uint(b.x)), "r"(__float_as_uint(b.y)));
}

__device__ __forceinline__ void cpa16(unsigned int dst, const void* src) {
    asm volatile("cp.async.cg.shared.global [%0], [%1], 16;" :: "r"(dst), "l"(src) : "memory");
}

// ---------------- K1: LN1 + feature-conv + both QKV projections --------------
#define SWS 289
#define K1_SMEM ((48*SWS + 8*192 + 288) * 4)

__global__ __launch_bounds__(256) void k1_ln_conv_qkv(
    const float* __restrict__ x,
    const float* __restrict__ ln1g, const float* __restrict__ ln1b,
    const float* __restrict__ accw, const float* __restrict__ accb,
    const float* __restrict__ gyrw, const float* __restrict__ gyrb,
    const float* __restrict__ convw)
{
    extern __shared__ float dsm[];
    float* swT   = dsm;
    float* sx    = dsm + 48*SWS;
    float* sbias = sx + 8*192;

    int tid = threadIdx.x;
    for (int idx = tid; idx < 144*48; idx += 256) {
        int row = idx / 48, i = idx % 48;
        swT[i*SWS + row]        = accw[idx];
        swT[i*SWS + 144 + row]  = gyrw[idx];
    }
    for (int j = tid; j < 288; j += 256)
        sbias[j] = (j < 144) ? accb[j] : gyrb[j-144];

    int warp = tid >> 5, lane = tid & 31;
    int t = blockIdx.x * 8 + warp;

    float v[6];
    float sum = 0.f, sq = 0.f;
    #pragma unroll
    for (int i = 0; i < 6; i++) {
        v[i] = x[(size_t)t*EE + lane + i*32];
        sum += v[i]; sq += v[i]*v[i];
    }
    #pragma unroll
    for (int o = 16; o > 0; o >>= 1) {
        sum += __shfl_xor_sync(0xffffffffu, sum, o);
        sq  += __shfl_xor_sync(0xffffffffu, sq,  o);
    }
    float mean = sum * (1.f/192.f);
    float var  = sq * (1.f/192.f) - mean*mean;
    float rstd = rsqrtf(var + 1e-6f);
    #pragma unroll
    for (int i = 0; i < 6; i++) {
        int f = lane + i*32;
        float xn = (v[i] - mean) * rstd * ln1g[f] + ln1b[f];
        sx[warp*192 + f] = xn;
    }
    __syncthreads();

    {
        int c = t & 3;
        float cw[15];
        #pragma unroll
        for (int k = 0; k < 15; k++) cw[k] = convw[c*15 + k];
        const float* xw = sx + warp*192 + 48;
        #pragma unroll
        for (int r = 0; r < 3; r++) {
            int w = lane + r*32;
            float acc = 0.f;
            #pragma unroll
            for (int k = 0; k < 15; k++) {
                int idx = w + k - 7;
                if (idx >= 0 && idx < 96) acc += cw[k] * xw[idx];
            }
            g_conv[t][w] = acc;
        }
    }

    {
        const float* xr = sx + warp*192;
        #pragma unroll
        for (int r = 0; r < 9; r++) {
            int j = lane + r*32;
            int gy = (j >= 144);
            const float* xb = xr + (gy ? 96 : 0);
            float acc = sbias[j];
            #pragma unroll
            for (int i = 0; i < 48; i++)
                acc += swT[i*SWS + j] * xb[i];
            if (gy) g_qkv[1][t][j-144] = acc;
            else    g_qkv[0][t][j]     = acc;
        }
    }
}

// ---------------- K2: tensor-core attention (tf32 mma, single-pass) ----------
#define K2_SMEM ((8192 + 8192 + 8*16*68) * 4)

__global__ __launch_bounds__(256) void k2_attn_mma()
{
    extern __shared__ float sm[];
    float* sK = sm;            // [(keytile8*2 + hdtile)*32 + lane]*2 + reg
    float* sV = sm + 8192;
    float* sP = sm + 16384;    // per warp [16][68]

    int tid = threadIdx.x;
    int qb   = blockIdx.x & 3;
    int rest = blockIdx.x >> 2;
    int h  = rest % NH;  rest /= NH;
    int b  = rest % BB;
    int br = rest / BB;
    int tbase = b * SS;

    for (int idx = tid; idx < SS*HD; idx += 256) {
        int key = idx >> 4, d = idx & 15;
        float kv = g_qkv[br][tbase+key][48 + h*16 + d];
        float vv = g_qkv[br][tbase+key][96 + h*16 + d];
        int laneK = (key & 7)*4 + (d & 3);
        sK[(((key>>3)*2 + (d>>3))*32 + laneK)*2 + ((d>>2)&1)] = tf32f(kv);
        int laneV = (d & 7)*4 + (key & 3);
        sV[(((key>>3)*2 + (d>>3))*32 + laneV)*2 + ((key>>2)&1)] = tf32f(vv);
    }

    int wq = tid >> 5, lane = tid & 31;
    int g = lane >> 2, t4 = lane & 3;
    int q0 = tbase + qb*128 + wq*16;

    float4 qa[2];
    {
        const float* qr0 = &g_qkv[br][q0+g][h*16];
        const float* qr1 = &g_qkv[br][q0+g+8][h*16];
        #pragma unroll
        for (int kt = 0; kt < 2; kt++) {
            qa[kt].x = tf32f(qr0[kt*8 + t4]     * 0.25f);
            qa[kt].y = tf32f(qr1[kt*8 + t4]     * 0.25f);
            qa[kt].z = tf32f(qr0[kt*8 + t4 + 4] * 0.25f);
            qa[kt].w = tf32f(qr1[kt*8 + t4 + 4] * 0.25f);
        }
    }
    __syncthreads();

    float4 oacc[2];
    oacc[0] = make_float4(0.f,0.f,0.f,0.f);
    oacc[1] = make_float4(0.f,0.f,0.f,0.f);
    float l0 = 0.f, l1 = 0.f;
    float* sPw = sP + wq*16*68;

    for (int kb = 0; kb < 8; kb++) {
        float4 sacc[8];
        #pragma unroll
        for (int ni = 0; ni < 8; ni++) sacc[ni] = make_float4(0.f,0.f,0.f,0.f);

        #pragma unroll
        for (int ni = 0; ni < 8; ni++) {
            int nt = kb*8 + ni;
            mma_tf32(sacc[ni], qa[0], *(const float2*)&sK[((nt*2+0)*32 + lane)*2]);
            mma_tf32(sacc[ni], qa[1], *(const float2*)&sK[((nt*2+1)*32 + lane)*2]);
        }
        #pragma unroll
        for (int ni = 0; ni < 8; ni++) {
            float px = __expf(sacc[ni].x), py = __expf(sacc[ni].y);
            float pz = __expf(sacc[ni].z), pw = __expf(sacc[ni].w);
            l0 += px + py; l1 += pz + pw;
            float2 hi = make_float2(tf32f(px), tf32f(py));
            float2 lo = make_float2(tf32f(pz), tf32f(pw));
            *(float2*)&sPw[ g   *68 + ni*8 + 2*t4] = hi;
            *(float2*)&sPw[(g+8)*68 + ni*8 + 2*t4] = lo;
        }
        __syncwarp();
        #pragma unroll
        for (int kt2 = 0; kt2 < 8; kt2++) {
            float4 af;
            af.x = sPw[ g   *68 + kt2*8 + t4];
            af.y = sPw[(g+8)*68 + kt2*8 + t4];
            af.z = sPw[ g   *68 + kt2*8 + t4 + 4];
            af.w = sPw[(g+8)*68 + kt2*8 + t4 + 4];
            int ktg = kb*8 + kt2;
            mma_tf32(oacc[0], af, *(const float2*)&sV[((ktg*2+0)*32 + lane)*2]);
            mma_tf32(oacc[1], af, *(const float2*)&sV[((ktg*2+1)*32 + lane)*2]);
        }
        __syncwarp();
    }

    l0 += __shfl_xor_sync(0xffffffffu, l0, 1);
    l0 += __shfl_xor_sync(0xffffffffu, l0, 2);
    l1 += __shfl_xor_sync(0xffffffffu, l1, 1);
    l1 += __shfl_xor_sync(0xffffffffu, l1, 2);
    float i0 = 1.f / l0, i1 = 1.f / l1;

    #pragma unroll
    for (int nt = 0; nt < 2; nt++) {
        int col = br*48 + h*16 + nt*8 + 2*t4;
        *(float2*)&g_att[q0+g  ][col] = make_float2(oacc[nt].x*i0, oacc[nt].y*i0);
        *(float2*)&g_att[q0+g+8][col] = make_float2(oacc[nt].z*i1, oacc[nt].w*i1);
    }
}

// ---------------- K3a: output projections + concat + residual + LN2 ----------
__global__ __launch_bounds__(256) void k3a_proj_ln2(
    const float* __restrict__ x,
    const float* __restrict__ accwo, const float* __restrict__ accbo,
    const float* __restrict__ gyrwo, const float* __restrict__ gyrbo,
    const float* __restrict__ ln2g, const float* __restrict__ ln2b)
{
    __shared__ float woT[48*97];
    __shared__ float satt[8][96];
    __shared__ float sproj[8][96];
    __shared__ float sb[96];

    int tid = threadIdx.x;
    for (int idx = tid; idx < 48*48; idx += 256) {
        int row = idx / 48, i = idx % 48;
        woT[i*97 + row]      = accwo[idx];
        woT[i*97 + 48 + row] = gyrwo[idx];
    }
    for (int j = tid; j < 96; j += 256)
        sb[j] = (j < 48) ? accbo[j] : gyrbo[j-48];

    int warp = tid >> 5, lane = tid & 31;
    int t = blockIdx.x * 8 + warp;

    #pragma unroll
    for (int r = 0; r < 3; r++)
        satt[warp][lane + r*32] = g_att[t][lane + r*32];
    __syncthreads();

    #pragma unroll
    for (int r = 0; r < 3; r++) {
        int j = lane + r*32;
        const float* ab = &satt[warp][(j < 48) ? 0 : 48];
        float acc = sb[j];
        #pragma unroll
        for (int i = 0; i < 48; i++)
            acc += woT[i*97 + j] * ab[i];
        sproj[warp][j] = acc;
    }
    __syncwarp();

    float xv[6];
    float sum = 0.f, sq = 0.f;
    #pragma unroll
    for (int i = 0; i < 6; i++) {
        int f = lane + i*32;
        float cv;
        if (f < 48)       cv = sproj[warp][f];
        else if (f < 144) cv = g_conv[t][f-48];
        else              cv = sproj[warp][48 + (f-144)];
        float x1 = cv + x[(size_t)t*EE + f];
        xv[i] = x1; sum += x1; sq += x1*x1;
    }
    #pragma unroll
    for (int o = 16; o > 0; o >>= 1) {
        sum += __shfl_xor_sync(0xffffffffu, sum, o);
        sq  += __shfl_xor_sync(0xffffffffu, sq,  o);
    }
    float mean = sum * (1.f/192.f);
    float var  = sq * (1.f/192.f) - mean*mean;
    float rstd = rsqrtf(var + 1e-6f);
    #pragma unroll
    for (int i = 0; i < 6; i++) {
        int f = lane + i*32;
        g_x1[t][f]  = xv[i];
        g_x1n[t][f] = (xv[i] - mean) * rstd * ln2g[f] + ln2b[f];
    }
}

// ---------------- tf32 GEMM v3: cp.async double-buffered, BK=32 --------------
// C = relu(A@Bw^T + bias) [+Res]. A [M,K] rm, Bw [N,K] rm. BM=128 BN=64.
// Raw fp32 in smem (HMMA.TF32 truncates mantissa). Stride-36 rows => scalar
// fragment LDS is bank-conflict-free: bank = (4g + t4) & 31 covers all 32.
#define GAS 36                         // padded row stride (floats)
#define G_ABUF (128*GAS)               // floats per A buffer
#define G_BBUF (64*GAS)
#define G_SMEM ((2*G_ABUF + 2*G_BBUF) * 4)   // 55296 B

__global__ __launch_bounds__(256) void gemm_tf32_v3(
    const float* __restrict__ A, const float* __restrict__ Bw,
    const float* __restrict__ bias, const float* __restrict__ Res,
    float* __restrict__ C, int N, int K)
{
    extern __shared__ float gsm[];
    float* sA = gsm;                   // [2][128][GAS]
    float* sB = gsm + 2*G_ABUF;        // [2][64][GAS]
    unsigned int sAu = (unsigned int)__cvta_generic_to_shared(sA);
    unsigned int sBu = (unsigned int)__cvta_generic_to_shared(sB);

    int tid  = threadIdx.x;
    int ms   = blockIdx.x * 128;
    int ns   = blockIdx.y * 64;
    int warp = tid >> 5, lane = tid & 31;
    int wm   = warp & 3;
    int wn   = warp >> 2;
    int g = lane >> 2, t4 = lane & 3;

    float4 acc[2][4];
    #pragma unroll
    for (int mi = 0; mi < 2; mi++)
        #pragma unroll
        for (int ni = 0; ni < 4; ni++)
            acc[mi][ni] = make_float4(0.f,0.f,0.f,0.f);

    // staging: A = 1024 16B-chunks (128 rows x 8), B = 512 chunks (64 rows x 8)
    int nIter = K >> 5;                     // K/32

    // prologue: stage buffers 0 and 1
    #pragma unroll
    for (int buf = 0; buf < 2; buf++) {
        int k0 = buf * 32;
        #pragma unroll
        for (int p = 0; p < 4; p++) {
            int c = tid + p*256;
            int row = c >> 3, off = (c & 7) * 4;
            cpa16(sAu + (unsigned int)((buf*G_ABUF + row*GAS + off)*4),
                  A + (size_t)(ms+row)*K + k0 + off);
        }
        #pragma unroll
        for (int p = 0; p < 2; p++) {
            int c = tid + p*256;
            int row = c >> 3, off = (c & 7) * 4;
            cpa16(sBu + (unsigned int)((buf*G_BBUF + row*GAS + off)*4),
                  Bw + (size_t)(ns+row)*K + k0 + off);
        }
        asm volatile("cp.async.commit_group;" ::: "memory");
    }

    for (int it = 0; it < nIter; it++) {
        if (it + 1 < nIter) asm volatile("cp.async.wait_group 1;" ::: "memory");
        else                asm volatile("cp.async.wait_group 0;" ::: "memory");
        __syncthreads();

        int buf = it & 1;
        const float* a = sA + buf*G_ABUF;
        const float* bsm = sB + buf*G_BBUF;

        #pragma unroll
        for (int kt = 0; kt < 4; kt++) {
            int kk = kt*8 + t4;
            float4 av[2];
            #pragma unroll
            for (int mi = 0; mi < 2; mi++) {
                int r0 = wm*32 + mi*16 + g;
                av[mi].x = a[r0*GAS + kk];
                av[mi].y = a[(r0+8)*GAS + kk];
                av[mi].z = a[r0*GAS + kk + 4];
                av[mi].w = a[(r0+8)*GAS + kk + 4];
            }
            #pragma unroll
            for (int ni = 0; ni < 4; ni++) {
                int n = wn*32 + ni*8 + g;
                float2 bf;
                bf.x = bsm[n*GAS + kk];
                bf.y = bsm[n*GAS + kk + 4];
                mma_tf32(acc[0][ni], av[0], bf);
                mma_tf32(acc[1][ni], av[1], bf);
            }
        }

        // stage buffer for iteration it+2 (reuses this buf)
        if (it + 2 < nIter) {
            __syncthreads();
            int k0 = (it + 2) * 32;
            #pragma unroll
            for (int p = 0; p < 4; p++) {
                int c = tid + p*256;
                int row = c >> 3, off = (c & 7) * 4;
                cpa16(sAu + (unsigned int)((buf*G_ABUF + row*GAS + off)*4),
                      A + (size_t)(ms+row)*K + k0 + off);
            }
            #pragma unroll
            for (int p = 0; p < 2; p++) {
                int c = tid + p*256;
                int row = c >> 3, off = (c & 7) * 4;
                cpa16(sBu + (unsigned int)((buf*G_BBUF + row*GAS + off)*4),
                      Bw + (size_t)(ns+row)*K + k0 + off);
            }
            asm volatile("cp.async.commit_group;" ::: "memory");
        }
    }

    // epilogue: bias + relu (+Res)
    #pragma unroll
    for (int mi = 0; mi < 2; mi++) {
        #pragma unroll
        for (int ni = 0; ni < 4; ni++) {
            int m0 = ms + wm*32 + mi*16 + g;
            int n  = ns + wn*32 + ni*8 + t4*2;
            float b0 = bias[n], b1 = bias[n+1];
            {
                float2 v;
                v.x = fmaxf(acc[mi][ni].x + b0, 0.f);
                v.y = fmaxf(acc[mi][ni].y + b1, 0.f);
                if (Res) { v.x += Res[(size_t)m0*N + n]; v.y += Res[(size_t)m0*N + n + 1]; }
                *(float2*)&C[(size_t)m0*N + n] = v;
            }
            {
                int m1 = m0 + 8;
                float2 v;
                v.x = fmaxf(acc[mi][ni].z + b0, 0.f);
                v.y = fmaxf(acc[mi][ni].w + b1, 0.f);
                if (Res) { v.x += Res[(size_t)m1*N + n]; v.y += Res[(size_t)m1*N + n + 1]; }
                *(float2*)&C[(size_t)m1*N + n] = v;
            }
        }
    }
}

// ---------------- launcher ----------------------------------------------------
extern "C" void kernel_launch(void* const* d_in, const int* in_sizes, int n_in,
                              void* d_out, int out_size)
{
    const float* x     = (const float*)d_in[0];
    const float* ln1g  = (const float*)d_in[1];
    const float* ln1b  = (const float*)d_in[2];
    const float* accw  = (const float*)d_in[3];
    const float* accb  = (const float*)d_in[4];
    const float* accwo = (const float*)d_in[5];
    const float* accbo = (const float*)d_in[6];
    const float* gyrw  = (const float*)d_in[7];
    const float* gyrb  = (const float*)d_in[8];
    const float* gyrwo = (const float*)d_in[9];
    const float* gyrbo = (const float*)d_in[10];
    const float* convw = (const float*)d_in[11];
    const float* ln2g  = (const float*)d_in[12];
    const float* ln2b  = (const float*)d_in[13];
    const float* w1    = (const float*)d_in[14];
    const float* b1    = (const float*)d_in[15];
    const float* w2    = (const float*)d_in[16];
    const float* b2    = (const float*)d_in[17];
    float* out = (float*)d_out;

    cudaFuncSetAttribute(k1_ln_conv_qkv, cudaFuncAttributeMaxDynamicSharedMemorySize, K1_SMEM);
    cudaFuncSetAttribute(k2_attn_mma,    cudaFuncAttributeMaxDynamicSharedMemorySize, K2_SMEM);
    cudaFuncSetAttribute(gemm_tf32_v3,   cudaFuncAttributeMaxDynamicSharedMemorySize, G_SMEM);

    void *p_x1, *p_x1n, *p_h;
    cudaGetSymbolAddress(&p_x1,  g_x1);
    cudaGetSymbolAddress(&p_x1n, g_x1n);
    cudaGetSymbolAddress(&p_h,   g_h);

    k1_ln_conv_qkv<<<TT/8, 256, K1_SMEM>>>(x, ln1g, ln1b, accw, accb, gyrw, gyrb, convw);
    k2_attn_mma<<<2*BB*NH*4, 256, K2_SMEM>>>();
    k3a_proj_ln2<<<TT/8, 256>>>(x, accwo, accbo, gyrwo, gyrbo, ln2g, ln2b);

    // MLP: h = relu(x1n @ w1^T + b1);  out = x1 + relu(h @ w2^T + b2)
    gemm_tf32_v3<<<dim3(TT/128, 384/64), 256, G_SMEM>>>(
        (const float*)p_x1n, w1, b1, nullptr, (float*)p_h, 384, 192);
    gemm_tf32_v3<<<dim3(TT/128, 192/64), 256, G_SMEM>>>(
        (const float*)p_h, w2, b2, (const float*)p_x1, out, 192, 384);
}

// round 10
// speedup vs baseline: 3.0947x; 1.2552x over previous
#include <cuda_runtime.h>
#include <cstdint>
#include <math.h>

#define BB 128
#define SS 512
#define EE 192
#define TT (BB*SS)      // 65536 tokens
#define QD 48
#define NH 3
#define HD 16

// ---------------- scratch (device globals; no allocation allowed) -------------
__device__ float g_xn[TT][EE];        // LN1 output
__device__ float g_qkv[2][TT][144];   // per branch: q[0:48] k[48:96] v[96:144]
__device__ float g_conv[TT][96];
__device__ float g_att[TT][96];       // acc heads 0:48, gyro heads 48:96 (pre-proj)
__device__ float g_x1[TT][EE];
__device__ float g_x1n[TT][EE];
__device__ float g_h[TT][384];

__device__ __forceinline__ unsigned f2tf32(float v) {
    unsigned u;
    asm("cvt.rna.tf32.f32 %0, %1;" : "=r"(u) : "f"(v));
    return u;
}
__device__ __forceinline__ float tf32f(float v) { return __uint_as_float(f2tf32(v)); }

__device__ __forceinline__ void mma_tf32(float4& c, const float4& a, const float2& b) {
    asm volatile(
        "mma.sync.aligned.m16n8k8.row.col.f32.tf32.tf32.f32 "
        "{%0,%1,%2,%3},{%4,%5,%6,%7},{%8,%9},{%0,%1,%2,%3};"
        : "+f"(c.x), "+f"(c.y), "+f"(c.z), "+f"(c.w)
        : "r"(__float_as_uint(a.x)), "r"(__float_as_uint(a.y)),
          "r"(__float_as_uint(a.z)), "r"(__float_as_uint(a.w)),
          "r"(__float_as_uint(b.x)), "r"(__float_as_uint(b.y)));
}

__device__ __forceinline__ void cpa16(unsigned int dst, const void* src) {
    asm volatile("cp.async.cg.shared.global [%0], [%1], 16;" :: "r"(dst), "l"(src) : "memory");
}

// ---------------- K1: LN1 + feature-conv (memory-bound) ----------------------
__global__ __launch_bounds__(256) void k1_ln_conv(
    const float* __restrict__ x,
    const float* __restrict__ ln1g, const float* __restrict__ ln1b,
    const float* __restrict__ convw)
{
    __shared__ float sx[8][192];

    int tid = threadIdx.x;
    int warp = tid >> 5, lane = tid & 31;
    int t = blockIdx.x * 8 + warp;

    float v[6];
    float sum = 0.f, sq = 0.f;
    #pragma unroll
    for (int i = 0; i < 6; i++) {
        v[i] = x[(size_t)t*EE + lane + i*32];
        sum += v[i]; sq += v[i]*v[i];
    }
    #pragma unroll
    for (int o = 16; o > 0; o >>= 1) {
        sum += __shfl_xor_sync(0xffffffffu, sum, o);
        sq  += __shfl_xor_sync(0xffffffffu, sq,  o);
    }
    float mean = sum * (1.f/192.f);
    float var  = sq * (1.f/192.f) - mean*mean;
    float rstd = rsqrtf(var + 1e-6f);
    #pragma unroll
    for (int i = 0; i < 6; i++) {
        int f = lane + i*32;
        float xn = (v[i] - mean) * rstd * ln1g[f] + ln1b[f];
        sx[warp][f] = xn;
        g_xn[t][f] = xn;
    }
    __syncwarp();

    // depthwise conv along feature axis (channel = token % 4)
    int c = t & 3;
    float cw[15];
    #pragma unroll
    for (int k = 0; k < 15; k++) cw[k] = convw[c*15 + k];
    const float* xw = &sx[warp][48];
    #pragma unroll
    for (int r = 0; r < 3; r++) {
        int w = lane + r*32;
        float acc = 0.f;
        #pragma unroll
        for (int k = 0; k < 15; k++) {
            int idx = w + k - 7;
            if (idx >= 0 && idx < 96) acc += cw[k] * xw[idx];
        }
        g_conv[t][w] = acc;
    }
}

// ---------------- K1b: QKV projections via tf32 mma --------------------------
// out[t][n], n in 0..287: n<144 -> acc branch (A slice cols 0:48),
//                         n>=144 -> gyro branch (A slice cols 96:144).
// BM=64, BN=288, K=48. 8 warps: wm in 0..1 (32 rows), wn in 0..3 (72 cols).
#define K1B_SAS 100                      // sA row stride (floats): 64 rows x [acc48|gyro48]
#define K1B_SBS 52                       // sB row stride
#define K1B_SMEM ((64*K1B_SAS + 288*K1B_SBS + 288) * 4)

__global__ __launch_bounds__(256) void k1b_qkv_mma(
    const float* __restrict__ accw, const float* __restrict__ accb,
    const float* __restrict__ gyrw, const float* __restrict__ gyrb)
{
    extern __shared__ float smm[];
    float* sA    = smm;                        // [64][100]
    float* sB    = smm + 64*K1B_SAS;           // [288][52]
    float* sbias = smm + 64*K1B_SAS + 288*K1B_SBS;

    int tid = threadIdx.x;
    int t0 = blockIdx.x * 64;

    // stage weights [288][48]
    for (int cc = tid; cc < 288*12; cc += 256) {
        int row = cc / 12, q = cc % 12;
        const float* src = (row < 144) ? &accw[row*48 + q*4] : &gyrw[(row-144)*48 + q*4];
        *(float4*)&sB[row*K1B_SBS + q*4] = *(const float4*)src;
    }
    for (int j = tid; j < 288; j += 256)
        sbias[j] = (j < 144) ? accb[j] : gyrb[j-144];

    // stage A: xn rows t0..t0+63, cols [0:48] -> 0:48, [96:144] -> 48:96
    for (int cc = tid; cc < 64*24; cc += 256) {
        int row = cc / 24, q = cc % 24;
        int srcc = (q < 12) ? q*4 : 96 + (q-12)*4;
        *(float4*)&sA[row*K1B_SAS + q*4] = *(const float4*)&g_xn[t0+row][srcc];
    }
    __syncthreads();

    int warp = tid >> 5, lane = tid & 31;
    int g = lane >> 2, t4 = lane & 3;
    int wm = warp & 1, wn = warp >> 1;
    int koff = (wn >= 2) ? 48 : 0;             // A slice select (warp-constant)

    float4 acc[2][9];
    #pragma unroll
    for (int mi = 0; mi < 2; mi++)
        #pragma unroll
        for (int ni = 0; ni < 9; ni++)
            acc[mi][ni] = make_float4(0.f,0.f,0.f,0.f);

    #pragma unroll
    for (int kt = 0; kt < 6; kt++) {
        float4 av[2];
        #pragma unroll
        for (int mi = 0; mi < 2; mi++) {
            int r0 = wm*32 + mi*16 + g;
            int kk = koff + kt*8 + t4;
            av[mi].x = sA[r0*K1B_SAS + kk];
            av[mi].y = sA[(r0+8)*K1B_SAS + kk];
            av[mi].z = sA[r0*K1B_SAS + kk + 4];
            av[mi].w = sA[(r0+8)*K1B_SAS + kk + 4];
        }
        #pragma unroll
        for (int ni = 0; ni < 9; ni++) {
            int n = wn*72 + ni*8 + g;
            float2 bf;
            bf.x = sB[n*K1B_SBS + kt*8 + t4];
            bf.y = sB[n*K1B_SBS + kt*8 + t4 + 4];
            mma_tf32(acc[0][ni], av[0], bf);
            mma_tf32(acc[1][ni], av[1], bf);
        }
    }

    // epilogue: bias, route to g_qkv[br]
    #pragma unroll
    for (int mi = 0; mi < 2; mi++) {
        #pragma unroll
        for (int ni = 0; ni < 9; ni++) {
            int m0 = t0 + wm*32 + mi*16 + g;
            int n  = wn*72 + ni*8 + t4*2;
            int br = (n >= 144);
            int col = n - br*144;
            float b0 = sbias[n], b1 = sbias[n+1];
            *(float2*)&g_qkv[br][m0][col]   = make_float2(acc[mi][ni].x + b0, acc[mi][ni].y + b1);
            *(float2*)&g_qkv[br][m0+8][col] = make_float2(acc[mi][ni].z + b0, acc[mi][ni].w + b1);
        }
    }
}

// ---------------- K2: tensor-core attention (tf32 mma, single-pass) ----------
// grid: 2*BB*NH*2 blocks; 8 warps, 32 queries/warp in 2 chunks of 16
#define K2_SMEM ((8192 + 8192 + 8*16*68) * 4)

__global__ __launch_bounds__(256) void k2_attn_mma()
{
    extern __shared__ float sm[];
    float* sK = sm;            // [(keytile8*2 + hdtile)*32 + lane]*2 + reg
    float* sV = sm + 8192;
    float* sP = sm + 16384;    // per warp [16][68]

    int tid = threadIdx.x;
    int qb   = blockIdx.x & 1;
    int rest = blockIdx.x >> 1;
    int h  = rest % NH;  rest /= NH;
    int b  = rest % BB;
    int br = rest / BB;
    int tbase = b * SS;

    for (int idx = tid; idx < SS*HD; idx += 256) {
        int key = idx >> 4, d = idx & 15;
        float kv = g_qkv[br][tbase+key][48 + h*16 + d];
        float vv = g_qkv[br][tbase+key][96 + h*16 + d];
        int laneK = (key & 7)*4 + (d & 3);
        sK[(((key>>3)*2 + (d>>3))*32 + laneK)*2 + ((d>>2)&1)] = tf32f(kv);
        int laneV = (d & 7)*4 + (key & 3);
        sV[(((key>>3)*2 + (d>>3))*32 + laneV)*2 + ((key>>2)&1)] = tf32f(vv);
    }

    int wq = tid >> 5, lane = tid & 31;
    int g = lane >> 2, t4 = lane & 3;
    int qbase = tbase + qb*256 + wq*32;

    float4 qa[2][2];
    #pragma unroll
    for (int c = 0; c < 2; c++) {
        const float* qr0 = &g_qkv[br][qbase + c*16 + g][h*16];
        const float* qr1 = &g_qkv[br][qbase + c*16 + g + 8][h*16];
        #pragma unroll
        for (int kt = 0; kt < 2; kt++) {
            qa[c][kt].x = tf32f(qr0[kt*8 + t4]     * 0.25f);
            qa[c][kt].y = tf32f(qr1[kt*8 + t4]     * 0.25f);
            qa[c][kt].z = tf32f(qr0[kt*8 + t4 + 4] * 0.25f);
            qa[c][kt].w = tf32f(qr1[kt*8 + t4 + 4] * 0.25f);
        }
    }
    __syncthreads();

    float4 oacc[2][2];
    float l0[2], l1[2];
    #pragma unroll
    for (int c = 0; c < 2; c++) {
        oacc[c][0] = make_float4(0.f,0.f,0.f,0.f);
        oacc[c][1] = make_float4(0.f,0.f,0.f,0.f);
        l0[c] = 0.f; l1[c] = 0.f;
    }
    float* sPw = sP + wq*16*68;

    for (int kb = 0; kb < 8; kb++) {
        #pragma unroll
        for (int c = 0; c < 2; c++) {
            float4 sacc[8];
            #pragma unroll
            for (int ni = 0; ni < 8; ni++) sacc[ni] = make_float4(0.f,0.f,0.f,0.f);

            #pragma unroll
            for (int ni = 0; ni < 8; ni++) {
                int nt = kb*8 + ni;
                mma_tf32(sacc[ni], qa[c][0], *(const float2*)&sK[((nt*2+0)*32 + lane)*2]);
                mma_tf32(sacc[ni], qa[c][1], *(const float2*)&sK[((nt*2+1)*32 + lane)*2]);
            }
            #pragma unroll
            for (int ni = 0; ni < 8; ni++) {
                float px = __expf(sacc[ni].x), py = __expf(sacc[ni].y);
                float pz = __expf(sacc[ni].z), pw = __expf(sacc[ni].w);
                l0[c] += px + py; l1[c] += pz + pw;
                float2 hi = make_float2(tf32f(px), tf32f(py));
                float2 lo = make_float2(tf32f(pz), tf32f(pw));
                *(float2*)&sPw[ g   *68 + ni*8 + 2*t4] = hi;
                *(float2*)&sPw[(g+8)*68 + ni*8 + 2*t4] = lo;
            }
            __syncwarp();
            #pragma unroll
            for (int kt2 = 0; kt2 < 8; kt2++) {
                float4 af;
                af.x = sPw[ g   *68 + kt2*8 + t4];
                af.y = sPw[(g+8)*68 + kt2*8 + t4];
                af.z = sPw[ g   *68 + kt2*8 + t4 + 4];
                af.w = sPw[(g+8)*68 + kt2*8 + t4 + 4];
                int ktg = kb*8 + kt2;
                mma_tf32(oacc[c][0], af, *(const float2*)&sV[((ktg*2+0)*32 + lane)*2]);
                mma_tf32(oacc[c][1], af, *(const float2*)&sV[((ktg*2+1)*32 + lane)*2]);
            }
            __syncwarp();
        }
    }

    #pragma unroll
    for (int c = 0; c < 2; c++) {
        float a0 = l0[c], a1 = l1[c];
        a0 += __shfl_xor_sync(0xffffffffu, a0, 1);
        a0 += __shfl_xor_sync(0xffffffffu, a0, 2);
        a1 += __shfl_xor_sync(0xffffffffu, a1, 1);
        a1 += __shfl_xor_sync(0xffffffffu, a1, 2);
        float i0 = 1.f / a0, i1 = 1.f / a1;
        int q0 = qbase + c*16;
        #pragma unroll
        for (int nt = 0; nt < 2; nt++) {
            int col = br*48 + h*16 + nt*8 + 2*t4;
            *(float2*)&g_att[q0+g  ][col] = make_float2(oacc[c][nt].x*i0, oacc[c][nt].y*i0);
            *(float2*)&g_att[q0+g+8][col] = make_float2(oacc[c][nt].z*i1, oacc[c][nt].w*i1);
        }
    }
}

// ---------------- K3a: output projections + concat + residual + LN2 ----------
__global__ __launch_bounds__(256) void k3a_proj_ln2(
    const float* __restrict__ x,
    const float* __restrict__ accwo, const float* __restrict__ accbo,
    const float* __restrict__ gyrwo, const float* __restrict__ gyrbo,
    const float* __restrict__ ln2g, const float* __restrict__ ln2b)
{
    __shared__ float woT[48*97];
    __shared__ float satt[8][96];
    __shared__ float sproj[8][96];
    __shared__ float sb[96];

    int tid = threadIdx.x;
    for (int idx = tid; idx < 48*48; idx += 256) {
        int row = idx / 48, i = idx % 48;
        woT[i*97 + row]      = accwo[idx];
        woT[i*97 + 48 + row] = gyrwo[idx];
    }
    for (int j = tid; j < 96; j += 256)
        sb[j] = (j < 48) ? accbo[j] : gyrbo[j-48];

    int warp = tid >> 5, lane = tid & 31;
    int t = blockIdx.x * 8 + warp;

    #pragma unroll
    for (int r = 0; r < 3; r++)
        satt[warp][lane + r*32] = g_att[t][lane + r*32];
    __syncthreads();

    #pragma unroll
    for (int r = 0; r < 3; r++) {
        int j = lane + r*32;
        const float* ab = &satt[warp][(j < 48) ? 0 : 48];
        float acc = sb[j];
        #pragma unroll
        for (int i = 0; i < 48; i++)
            acc += woT[i*97 + j] * ab[i];
        sproj[warp][j] = acc;
    }
    __syncwarp();

    float xv[6];
    float sum = 0.f, sq = 0.f;
    #pragma unroll
    for (int i = 0; i < 6; i++) {
        int f = lane + i*32;
        float cv;
        if (f < 48)       cv = sproj[warp][f];
        else if (f < 144) cv = g_conv[t][f-48];
        else              cv = sproj[warp][48 + (f-144)];
        float x1 = cv + x[(size_t)t*EE + f];
        xv[i] = x1; sum += x1; sq += x1*x1;
    }
    #pragma unroll
    for (int o = 16; o > 0; o >>= 1) {
        sum += __shfl_xor_sync(0xffffffffu, sum, o);
        sq  += __shfl_xor_sync(0xffffffffu, sq,  o);
    }
    float mean = sum * (1.f/192.f);
    float var  = sq * (1.f/192.f) - mean*mean;
    float rstd = rsqrtf(var + 1e-6f);
    #pragma unroll
    for (int i = 0; i < 6; i++) {
        int f = lane + i*32;
        g_x1[t][f]  = xv[i];
        g_x1n[t][f] = (xv[i] - mean) * rstd * ln2g[f] + ln2b[f];
    }
}

// ---------------- tf32 GEMM v3: cp.async double-buffered, BK=32 --------------
#define GAS 36
#define G_ABUF (128*GAS)
#define G_BBUF (64*GAS)
#define G_SMEM ((2*G_ABUF + 2*G_BBUF) * 4)   // 55296 B

__global__ __launch_bounds__(256) void gemm_tf32_v3(
    const float* __restrict__ A, const float* __restrict__ Bw,
    const float* __restrict__ bias, const float* __restrict__ Res,
    float* __restrict__ C, int N, int K)
{
    extern __shared__ float gsm[];
    float* sA = gsm;                   // [2][128][GAS]
    float* sB = gsm + 2*G_ABUF;        // [2][64][GAS]
    unsigned int sAu = (unsigned int)__cvta_generic_to_shared(sA);
    unsigned int sBu = (unsigned int)__cvta_generic_to_shared(sB);

    int tid  = threadIdx.x;
    int ms   = blockIdx.x * 128;
    int ns   = blockIdx.y * 64;
    int warp = tid >> 5, lane = tid & 31;
    int wm   = warp & 3;
    int wn   = warp >> 2;
    int g = lane >> 2, t4 = lane & 3;

    float4 acc[2][4];
    #pragma unroll
    for (int mi = 0; mi < 2; mi++)
        #pragma unroll
        for (int ni = 0; ni < 4; ni++)
            acc[mi][ni] = make_float4(0.f,0.f,0.f,0.f);

    int nIter = K >> 5;                     // K/32

    #pragma unroll
    for (int buf = 0; buf < 2; buf++) {
        int k0 = buf * 32;
        #pragma unroll
        for (int p = 0; p < 4; p++) {
            int c = tid + p*256;
            int row = c >> 3, off = (c & 7) * 4;
            cpa16(sAu + (unsigned int)((buf*G_ABUF + row*GAS + off)*4),
                  A + (size_t)(ms+row)*K + k0 + off);
        }
        #pragma unroll
        for (int p = 0; p < 2; p++) {
            int c = tid + p*256;
            int row = c >> 3, off = (c & 7) * 4;
            cpa16(sBu + (unsigned int)((buf*G_BBUF + row*GAS + off)*4),
                  Bw + (size_t)(ns+row)*K + k0 + off);
        }
        asm volatile("cp.async.commit_group;" ::: "memory");
    }

    for (int it = 0; it < nIter; it++) {
        if (it + 1 < nIter) asm volatile("cp.async.wait_group 1;" ::: "memory");
        else                asm volatile("cp.async.wait_group 0;" ::: "memory");
        __syncthreads();

        int buf = it & 1;
        const float* a = sA + buf*G_ABUF;
        const float* bsm = sB + buf*G_BBUF;

        #pragma unroll
        for (int kt = 0; kt < 4; kt++) {
            int kk = kt*8 + t4;
            float4 av[2];
            #pragma unroll
            for (int mi = 0; mi < 2; mi++) {
                int r0 = wm*32 + mi*16 + g;
                av[mi].x = a[r0*GAS + kk];
                av[mi].y = a[(r0+8)*GAS + kk];
                av[mi].z = a[r0*GAS + kk + 4];
                av[mi].w = a[(r0+8)*GAS + kk + 4];
            }
            #pragma unroll
            for (int ni = 0; ni < 4; ni++) {
                int n = wn*32 + ni*8 + g;
                float2 bf;
                bf.x = bsm[n*GAS + kk];
                bf.y = bsm[n*GAS + kk + 4];
                mma_tf32(acc[0][ni], av[0], bf);
                mma_tf32(acc[1][ni], av[1], bf);
            }
        }

        if (it + 2 < nIter) {
            __syncthreads();
            int k0 = (it + 2) * 32;
            #pragma unroll
            for (int p = 0; p < 4; p++) {
                int c = tid + p*256;
                int row = c >> 3, off = (c & 7) * 4;
                cpa16(sAu + (unsigned int)((buf*G_ABUF + row*GAS + off)*4),
                      A + (size_t)(ms+row)*K + k0 + off);
            }
            #pragma unroll
            for (int p = 0; p < 2; p++) {
                int c = tid + p*256;
                int row = c >> 3, off = (c & 7) * 4;
                cpa16(sBu + (unsigned int)((buf*G_BBUF + row*GAS + off)*4),
                      Bw + (size_t)(ns+row)*K + k0 + off);
            }
            asm volatile("cp.async.commit_group;" ::: "memory");
        }
    }

    #pragma unroll
    for (int mi = 0; mi < 2; mi++) {
        #pragma unroll
        for (int ni = 0; ni < 4; ni++) {
            int m0 = ms + wm*32 + mi*16 + g;
            int n  = ns + wn*32 + ni*8 + t4*2;
            float b0 = bias[n], b1 = bias[n+1];
            {
                float2 v;
                v.x = fmaxf(acc[mi][ni].x + b0, 0.f);
                v.y = fmaxf(acc[mi][ni].y + b1, 0.f);
                if (Res) { v.x += Res[(size_t)m0*N + n]; v.y += Res[(size_t)m0*N + n + 1]; }
                *(float2*)&C[(size_t)m0*N + n] = v;
            }
            {
                int m1 = m0 + 8;
                float2 v;
                v.x = fmaxf(acc[mi][ni].z + b0, 0.f);
                v.y = fmaxf(acc[mi][ni].w + b1, 0.f);
                if (Res) { v.x += Res[(size_t)m1*N + n]; v.y += Res[(size_t)m1*N + n + 1]; }
                *(float2*)&C[(size_t)m1*N + n] = v;
            }
        }
    }
}

// ---------------- launcher ----------------------------------------------------
extern "C" void kernel_launch(void* const* d_in, const int* in_sizes, int n_in,
                              void* d_out, int out_size)
{
    const float* x     = (const float*)d_in[0];
    const float* ln1g  = (const float*)d_in[1];
    const float* ln1b  = (const float*)d_in[2];
    const float* accw  = (const float*)d_in[3];
    const float* accb  = (const float*)d_in[4];
    const float* accwo = (const float*)d_in[5];
    const float* accbo = (const float*)d_in[6];
    const float* gyrw  = (const float*)d_in[7];
    const float* gyrb  = (const float*)d_in[8];
    const float* gyrwo = (const float*)d_in[9];
    const float* gyrbo = (const float*)d_in[10];
    const float* convw = (const float*)d_in[11];
    const float* ln2g  = (const float*)d_in[12];
    const float* ln2b  = (const float*)d_in[13];
    const float* w1    = (const float*)d_in[14];
    const float* b1    = (const float*)d_in[15];
    const float* w2    = (const float*)d_in[16];
    const float* b2    = (const float*)d_in[17];
    float* out = (float*)d_out;

    cudaFuncSetAttribute(k1b_qkv_mma,  cudaFuncAttributeMaxDynamicSharedMemorySize, K1B_SMEM);
    cudaFuncSetAttribute(k2_attn_mma,  cudaFuncAttributeMaxDynamicSharedMemorySize, K2_SMEM);
    cudaFuncSetAttribute(gemm_tf32_v3, cudaFuncAttributeMaxDynamicSharedMemorySize, G_SMEM);

    void *p_x1, *p_x1n, *p_h;
    cudaGetSymbolAddress(&p_x1,  g_x1);
    cudaGetSymbolAddress(&p_x1n, g_x1n);
    cudaGetSymbolAddress(&p_h,   g_h);

    k1_ln_conv<<<TT/8, 256>>>(x, ln1g, ln1b, convw);
    k1b_qkv_mma<<<TT/64, 256, K1B_SMEM>>>(accw, accb, gyrw, gyrb);
    k2_attn_mma<<<2*BB*NH*2, 256, K2_SMEM>>>();
    k3a_proj_ln2<<<TT/8, 256>>>(x, accwo, accbo, gyrwo, gyrbo, ln2g, ln2b);

    // MLP: h = relu(x1n @ w1^T + b1);  out = x1 + relu(h @ w2^T + b2)
    gemm_tf32_v3<<<dim3(TT/128, 384/64), 256, G_SMEM>>>(
        (const float*)p_x1n, w1, b1, nullptr, (float*)p_h, 384, 192);
    gemm_tf32_v3<<<dim3(TT/128, 192/64), 256, G_SMEM>>>(
        (const float*)p_h, w2, b2, (const float*)p_x1, out, 192, 384);
}

// round 12
// speedup vs baseline: 3.3179x; 1.0721x over previous
#include <cuda_runtime.h>
#include <cstdint>
#include <math.h>

#define BB 128
#define SS 512
#define EE 192
#define TT (BB*SS)      // 65536 tokens
#define QD 48
#define NH 3
#define HD 16

// ---------------- scratch (device globals; no allocation allowed) -------------
__device__ float g_xn[TT][EE];        // LN1 output
__device__ float g_qkv[2][TT][144];   // per branch: q[0:48] k[48:96] v[96:144]
__device__ float g_conv[TT][96];
__device__ float g_att[TT][96];       // acc heads 0:48, gyro heads 48:96 (pre-proj)
__device__ float g_x1[TT][EE];
__device__ float g_x1n[TT][EE];
__device__ float g_h[TT][384];

__device__ __forceinline__ unsigned f2tf32(float v) {
    unsigned u;
    asm("cvt.rna.tf32.f32 %0, %1;" : "=r"(u) : "f"(v));
    return u;
}
__device__ __forceinline__ float tf32f(float v) { return __uint_as_float(f2tf32(v)); }

__device__ __forceinline__ void mma_tf32(float4& c, const float4& a, const float2& b) {
    asm volatile(
        "mma.sync.aligned.m16n8k8.row.col.f32.tf32.tf32.f32 "
        "{%0,%1,%2,%3},{%4,%5,%6,%7},{%8,%9},{%0,%1,%2,%3};"
        : "+f"(c.x), "+f"(c.y), "+f"(c.z), "+f"(c.w)
        : "r"(__float_as_uint(a.x)), "r"(__float_as_uint(a.y)),
          "r"(__float_as_uint(a.z)), "r"(__float_as_uint(a.w)),
          "r"(__float_as_uint(b.x)), "r"(__float_as_uint(b.y)));
}

__device__ __forceinline__ void cpa16(unsigned int dst, const void* src) {
    asm volatile("cp.async.cg.shared.global [%0], [%1], 16;" :: "r"(dst), "l"(src) : "memory");
}

// ---------------- K1: LN1 + feature-conv (memory-bound) ----------------------
__global__ __launch_bounds__(256) void k1_ln_conv(
    const float* __restrict__ x,
    const float* __restrict__ ln1g, const float* __restrict__ ln1b,
    const float* __restrict__ convw)
{
    __shared__ float sx[8][192];

    int tid = threadIdx.x;
    int warp = tid >> 5, lane = tid & 31;
    int t = blockIdx.x * 8 + warp;

    float v[6];
    float sum = 0.f, sq = 0.f;
    #pragma unroll
    for (int i = 0; i < 6; i++) {
        v[i] = x[(size_t)t*EE + lane + i*32];
        sum += v[i]; sq += v[i]*v[i];
    }
    #pragma unroll
    for (int o = 16; o > 0; o >>= 1) {
        sum += __shfl_xor_sync(0xffffffffu, sum, o);
        sq  += __shfl_xor_sync(0xffffffffu, sq,  o);
    }
    float mean = sum * (1.f/192.f);
    float var  = sq * (1.f/192.f) - mean*mean;
    float rstd = rsqrtf(var + 1e-6f);
    #pragma unroll
    for (int i = 0; i < 6; i++) {
        int f = lane + i*32;
        float xn = (v[i] - mean) * rstd * ln1g[f] + ln1b[f];
        sx[warp][f] = xn;
        g_xn[t][f] = xn;
    }
    __syncwarp();

    // depthwise conv along feature axis (channel = token % 4)
    int c = t & 3;
    float cw[15];
    #pragma unroll
    for (int k = 0; k < 15; k++) cw[k] = convw[c*15 + k];
    const float* xw = &sx[warp][48];
    #pragma unroll
    for (int r = 0; r < 3; r++) {
        int w = lane + r*32;
        float acc = 0.f;
        #pragma unroll
        for (int k = 0; k < 15; k++) {
            int idx = w + k - 7;
            if (idx >= 0 && idx < 96) acc += cw[k] * xw[idx];
        }
        g_conv[t][w] = acc;
    }
}

// ---------------- K1b: QKV projections via tf32 mma --------------------------
#define K1B_SAS 100
#define K1B_SBS 52
#define K1B_SMEM ((64*K1B_SAS + 288*K1B_SBS + 288) * 4)

__global__ __launch_bounds__(256) void k1b_qkv_mma(
    const float* __restrict__ accw, const float* __restrict__ accb,
    const float* __restrict__ gyrw, const float* __restrict__ gyrb)
{
    extern __shared__ float smm[];
    float* sA    = smm;                        // [64][100]
    float* sB    = smm + 64*K1B_SAS;           // [288][52]
    float* sbias = smm + 64*K1B_SAS + 288*K1B_SBS;

    int tid = threadIdx.x;
    int t0 = blockIdx.x * 64;

    for (int cc = tid; cc < 288*12; cc += 256) {
        int row = cc / 12, q = cc % 12;
        const float* src = (row < 144) ? &accw[row*48 + q*4] : &gyrw[(row-144)*48 + q*4];
        *(float4*)&sB[row*K1B_SBS + q*4] = *(const float4*)src;
    }
    for (int j = tid; j < 288; j += 256)
        sbias[j] = (j < 144) ? accb[j] : gyrb[j-144];

    for (int cc = tid; cc < 64*24; cc += 256) {
        int row = cc / 24, q = cc % 24;
        int srcc = (q < 12) ? q*4 : 96 + (q-12)*4;
        *(float4*)&sA[row*K1B_SAS + q*4] = *(const float4*)&g_xn[t0+row][srcc];
    }
    __syncthreads();

    int warp = tid >> 5, lane = tid & 31;
    int g = lane >> 2, t4 = lane & 3;
    int wm = warp & 1, wn = warp >> 1;
    int koff = (wn >= 2) ? 48 : 0;

    float4 acc[2][9];
    #pragma unroll
    for (int mi = 0; mi < 2; mi++)
        #pragma unroll
        for (int ni = 0; ni < 9; ni++)
            acc[mi][ni] = make_float4(0.f,0.f,0.f,0.f);

    #pragma unroll
    for (int kt = 0; kt < 6; kt++) {
        float4 av[2];
        #pragma unroll
        for (int mi = 0; mi < 2; mi++) {
            int r0 = wm*32 + mi*16 + g;
            int kk = koff + kt*8 + t4;
            av[mi].x = sA[r0*K1B_SAS + kk];
            av[mi].y = sA[(r0+8)*K1B_SAS + kk];
            av[mi].z = sA[r0*K1B_SAS + kk + 4];
            av[mi].w = sA[(r0+8)*K1B_SAS + kk + 4];
        }
        #pragma unroll
        for (int ni = 0; ni < 9; ni++) {
            int n = wn*72 + ni*8 + g;
            float2 bf;
            bf.x = sB[n*K1B_SBS + kt*8 + t4];
            bf.y = sB[n*K1B_SBS + kt*8 + t4 + 4];
            mma_tf32(acc[0][ni], av[0], bf);
            mma_tf32(acc[1][ni], av[1], bf);
        }
    }

    #pragma unroll
    for (int mi = 0; mi < 2; mi++) {
        #pragma unroll
        for (int ni = 0; ni < 9; ni++) {
            int m0 = t0 + wm*32 + mi*16 + g;
            int n  = wn*72 + ni*8 + t4*2;
            int br = (n >= 144);
            int col = n - br*144;
            float b0 = sbias[n], b1 = sbias[n+1];
            *(float2*)&g_qkv[br][m0][col]   = make_float2(acc[mi][ni].x + b0, acc[mi][ni].y + b1);
            *(float2*)&g_qkv[br][m0+8][col] = make_float2(acc[mi][ni].z + b0, acc[mi][ni].w + b1);
        }
    }
}

// ---------------- K2: tensor-core attention (tf32 mma, single-pass) ----------
// grid: 2*BB*NH*2 blocks; 8 warps, 32 queries/warp in 2 chunks of 16
#define K2_SMEM ((8192 + 8192 + 8*16*68) * 4)
#define QSCALE (0.25f * 1.44269504088896340736f)   // fold log2e: exp(s/4)=exp2(s*QSCALE)

__global__ __launch_bounds__(256) void k2_attn_mma()
{
    extern __shared__ float sm[];
    float* sK = sm;            // [(keytile8*2 + hdtile)*32 + lane]*2 + reg
    float* sV = sm + 8192;
    float* sP = sm + 16384;    // per warp [16][68]

    int tid = threadIdx.x;
    int qb   = blockIdx.x & 1;
    int rest = blockIdx.x >> 1;
    int h  = rest % NH;  rest /= NH;
    int b  = rest % BB;
    int br = rest / BB;
    int tbase = b * SS;

    for (int idx = tid; idx < SS*HD; idx += 256) {
        int key = idx >> 4, d = idx & 15;
        float kv = g_qkv[br][tbase+key][48 + h*16 + d];
        float vv = g_qkv[br][tbase+key][96 + h*16 + d];
        int laneK = (key & 7)*4 + (d & 3);
        sK[(((key>>3)*2 + (d>>3))*32 + laneK)*2 + ((d>>2)&1)] = tf32f(kv);
        int laneV = (d & 7)*4 + (key & 3);
        sV[(((key>>3)*2 + (d>>3))*32 + laneV)*2 + ((key>>2)&1)] = tf32f(vv);
    }

    int wq = tid >> 5, lane = tid & 31;
    int g = lane >> 2, t4 = lane & 3;
    int qbase = tbase + qb*256 + wq*32;

    float4 qa[2][2];
    #pragma unroll
    for (int c = 0; c < 2; c++) {
        const float* qr0 = &g_qkv[br][qbase + c*16 + g][h*16];
        const float* qr1 = &g_qkv[br][qbase + c*16 + g + 8][h*16];
        #pragma unroll
        for (int kt = 0; kt < 2; kt++) {
            qa[c][kt].x = tf32f(qr0[kt*8 + t4]     * QSCALE);
            qa[c][kt].y = tf32f(qr1[kt*8 + t4]     * QSCALE);
            qa[c][kt].z = tf32f(qr0[kt*8 + t4 + 4] * QSCALE);
            qa[c][kt].w = tf32f(qr1[kt*8 + t4 + 4] * QSCALE);
        }
    }
    __syncthreads();

    float4 oacc[2][2];
    float l0[2], l1[2];
    #pragma unroll
    for (int c = 0; c < 2; c++) {
        oacc[c][0] = make_float4(0.f,0.f,0.f,0.f);
        oacc[c][1] = make_float4(0.f,0.f,0.f,0.f);
        l0[c] = 0.f; l1[c] = 0.f;
    }
    float* sPw = sP + wq*16*68;

    for (int kb = 0; kb < 8; kb++) {
        #pragma unroll
        for (int c = 0; c < 2; c++) {
            float4 sacc[8];
            #pragma unroll
            for (int ni = 0; ni < 8; ni++) sacc[ni] = make_float4(0.f,0.f,0.f,0.f);

            #pragma unroll
            for (int ni = 0; ni < 8; ni++) {
                int nt = kb*8 + ni;
                mma_tf32(sacc[ni], qa[c][0], *(const float2*)&sK[((nt*2+0)*32 + lane)*2]);
                mma_tf32(sacc[ni], qa[c][1], *(const float2*)&sK[((nt*2+1)*32 + lane)*2]);
            }
            #pragma unroll
            for (int ni = 0; ni < 8; ni++) {
                float px = exp2f(sacc[ni].x), py = exp2f(sacc[ni].y);
                float pz = exp2f(sacc[ni].z), pw = exp2f(sacc[ni].w);
                l0[c] += px + py; l1[c] += pz + pw;
                float2 hi = make_float2(tf32f(px), tf32f(py));
                float2 lo = make_float2(tf32f(pz), tf32f(pw));
                *(float2*)&sPw[ g   *68 + ni*8 + 2*t4] = hi;
                *(float2*)&sPw[(g+8)*68 + ni*8 + 2*t4] = lo;
            }
            __syncwarp();
            #pragma unroll
            for (int kt2 = 0; kt2 < 8; kt2++) {
                float4 af;
                af.x = sPw[ g   *68 + kt2*8 + t4];
                af.y = sPw[(g+8)*68 + kt2*8 + t4];
                af.z = sPw[ g   *68 + kt2*8 + t4 + 4];
                af.w = sPw[(g+8)*68 + kt2*8 + t4 + 4];
                int ktg = kb*8 + kt2;
                mma_tf32(oacc[c][0], af, *(const float2*)&sV[((ktg*2+0)*32 + lane)*2]);
                mma_tf32(oacc[c][1], af, *(const float2*)&sV[((ktg*2+1)*32 + lane)*2]);
            }
            __syncwarp();
        }
    }

    #pragma unroll
    for (int c = 0; c < 2; c++) {
        float a0 = l0[c], a1 = l1[c];
        a0 += __shfl_xor_sync(0xffffffffu, a0, 1);
        a0 += __shfl_xor_sync(0xffffffffu, a0, 2);
        a1 += __shfl_xor_sync(0xffffffffu, a1, 1);
        a1 += __shfl_xor_sync(0xffffffffu, a1, 2);
        float i0 = 1.f / a0, i1 = 1.f / a1;
        int q0 = qbase + c*16;
        #pragma unroll
        for (int nt = 0; nt < 2; nt++) {
            int col = br*48 + h*16 + nt*8 + 2*t4;
            *(float2*)&g_att[q0+g  ][col] = make_float2(oacc[c][nt].x*i0, oacc[c][nt].y*i0);
            *(float2*)&g_att[q0+g+8][col] = make_float2(oacc[c][nt].z*i1, oacc[c][nt].w*i1);
        }
    }
}

// ---------------- K3: output projections (tf32 mma) + concat + res + LN2 -----
// block = 64 tokens, 256 threads. Proj: M=64, N=96, K=48 (branch by out col).
#define K3_SAS 100
#define K3_SPS 100
#define K3_SBS 52
#define K3_SMEM ((64*K3_SAS + 64*K3_SPS + 96*K3_SBS + 96) * 4)

__global__ __launch_bounds__(256) void k3_proj_ln2_mma(
    const float* __restrict__ x,
    const float* __restrict__ accwo, const float* __restrict__ accbo,
    const float* __restrict__ gyrwo, const float* __restrict__ gyrbo,
    const float* __restrict__ ln2g, const float* __restrict__ ln2b)
{
    extern __shared__ float smm[];
    float* sA    = smm;                          // [64][100] att rows
    float* sPj   = smm + 64*K3_SAS;              // [64][100] proj result
    float* sW    = smm + 64*K3_SAS + 64*K3_SPS;  // [96][52]
    float* sbias = sW + 96*K3_SBS;               // [96]

    int tid = threadIdx.x;
    int t0 = blockIdx.x * 64;

    // stage weights: row n = output col; n<48 acc, n>=48 gyro
    for (int cc = tid; cc < 96*12; cc += 256) {
        int row = cc / 12, q = cc % 12;
        const float* src = (row < 48) ? &accwo[row*48 + q*4] : &gyrwo[(row-48)*48 + q*4];
        *(float4*)&sW[row*K3_SBS + q*4] = *(const float4*)src;
    }
    for (int j = tid; j < 96; j += 256)
        sbias[j] = (j < 48) ? accbo[j] : gyrbo[j-48];

    // stage att rows [64][96]
    for (int cc = tid; cc < 64*24; cc += 256) {
        int row = cc / 24, q = cc % 24;
        *(float4*)&sA[row*K3_SAS + q*4] = *(const float4*)&g_att[t0+row][q*4];
    }
    __syncthreads();

    int warp = tid >> 5, lane = tid & 31;
    int g = lane >> 2, t4 = lane & 3;
    int wm = warp & 1, wn = warp >> 1;          // wm: 32 rows; wn: 24 cols
    int koff = (wn >= 2) ? 48 : 0;              // acc cols read att[0:48], gyro att[48:96]

    float4 acc[2][3];
    #pragma unroll
    for (int mi = 0; mi < 2; mi++)
        #pragma unroll
        for (int ni = 0; ni < 3; ni++)
            acc[mi][ni] = make_float4(0.f,0.f,0.f,0.f);

    #pragma unroll
    for (int kt = 0; kt < 6; kt++) {
        float4 av[2];
        #pragma unroll
        for (int mi = 0; mi < 2; mi++) {
            int r0 = wm*32 + mi*16 + g;
            int kk = koff + kt*8 + t4;
            av[mi].x = sA[r0*K3_SAS + kk];
            av[mi].y = sA[(r0+8)*K3_SAS + kk];
            av[mi].z = sA[r0*K3_SAS + kk + 4];
            av[mi].w = sA[(r0+8)*K3_SAS + kk + 4];
        }
        #pragma unroll
        for (int ni = 0; ni < 3; ni++) {
            int n = wn*24 + ni*8 + g;
            float2 bf;
            bf.x = sW[n*K3_SBS + kt*8 + t4];
            bf.y = sW[n*K3_SBS + kt*8 + t4 + 4];
            mma_tf32(acc[0][ni], av[0], bf);
            mma_tf32(acc[1][ni], av[1], bf);
        }
    }

    // write proj to smem (+bias)
    #pragma unroll
    for (int mi = 0; mi < 2; mi++) {
        #pragma unroll
        for (int ni = 0; ni < 3; ni++) {
            int m0 = wm*32 + mi*16 + g;
            int n  = wn*24 + ni*8 + t4*2;
            float b0 = sbias[n], b1 = sbias[n+1];
            *(float2*)&sPj[m0*K3_SPS + n]     = make_float2(acc[mi][ni].x + b0, acc[mi][ni].y + b1);
            *(float2*)&sPj[(m0+8)*K3_SPS + n] = make_float2(acc[mi][ni].z + b0, acc[mi][ni].w + b1);
        }
    }
    __syncthreads();

    // LN2 phase: warp per token, 8 tokens per warp
    for (int tt = 0; tt < 8; tt++) {
        int tl = warp*8 + tt;           // local token
        int t  = t0 + tl;
        float xv[6];
        float sum = 0.f, sq = 0.f;
        #pragma unroll
        for (int i = 0; i < 6; i++) {
            int f = lane + i*32;
            float cv;
            if (f < 48)       cv = sPj[tl*K3_SPS + f];
            else if (f < 144) cv = g_conv[t][f-48];
            else              cv = sPj[tl*K3_SPS + f - 96];
            float x1 = cv + x[(size_t)t*EE + f];
            xv[i] = x1; sum += x1; sq += x1*x1;
        }
        #pragma unroll
        for (int o = 16; o > 0; o >>= 1) {
            sum += __shfl_xor_sync(0xffffffffu, sum, o);
            sq  += __shfl_xor_sync(0xffffffffu, sq,  o);
        }
        float mean = sum * (1.f/192.f);
        float var  = sq * (1.f/192.f) - mean*mean;
        float rstd = rsqrtf(var + 1e-6f);
        #pragma unroll
        for (int i = 0; i < 6; i++) {
            int f = lane + i*32;
            g_x1[t][f]  = xv[i];
            g_x1n[t][f] = (xv[i] - mean) * rstd * ln2g[f] + ln2b[f];
        }
    }
}

// ---------------- tf32 GEMM v3: cp.async double-buffered, BK=32 --------------
#define GAS 36
#define G_ABUF (128*GAS)
#define G_BBUF (64*GAS)
#define G_SMEM ((2*G_ABUF + 2*G_BBUF) * 4)   // 55296 B

__global__ __launch_bounds__(256) void gemm_tf32_v3(
    const float* __restrict__ A, const float* __restrict__ Bw,
    const float* __restrict__ bias, const float* __restrict__ Res,
    float* __restrict__ C, int N, int K)
{
    extern __shared__ float gsm[];
    float* sA = gsm;                   // [2][128][GAS]
    float* sB = gsm + 2*G_ABUF;        // [2][64][GAS]
    unsigned int sAu = (unsigned int)__cvta_generic_to_shared(sA);
    unsigned int sBu = (unsigned int)__cvta_generic_to_shared(sB);

    int tid  = threadIdx.x;
    int ms   = blockIdx.x * 128;
    int ns   = blockIdx.y * 64;
    int warp = tid >> 5, lane = tid & 31;
    int wm   = warp & 3;
    int wn   = warp >> 2;
    int g = lane >> 2, t4 = lane & 3;

    float4 acc[2][4];
    #pragma unroll
    for (int mi = 0; mi < 2; mi++)
        #pragma unroll
        for (int ni = 0; ni < 4; ni++)
            acc[mi][ni] = make_float4(0.f,0.f,0.f,0.f);

    int nIter = K >> 5;                     // K/32

    #pragma unroll
    for (int buf = 0; buf < 2; buf++) {
        int k0 = buf * 32;
        #pragma unroll
        for (int p = 0; p < 4; p++) {
            int c = tid + p*256;
            int row = c >> 3, off = (c & 7) * 4;
            cpa16(sAu + (unsigned int)((buf*G_ABUF + row*GAS + off)*4),
                  A + (size_t)(ms+row)*K + k0 + off);
        }
        #pragma unroll
        for (int p = 0; p < 2; p++) {
            int c = tid + p*256;
            int row = c >> 3, off = (c & 7) * 4;
            cpa16(sBu + (unsigned int)((buf*G_BBUF + row*GAS + off)*4),
                  Bw + (size_t)(ns+row)*K + k0 + off);
        }
        asm volatile("cp.async.commit_group;" ::: "memory");
    }

    for (int it = 0; it < nIter; it++) {
        if (it + 1 < nIter) asm volatile("cp.async.wait_group 1;" ::: "memory");
        else                asm volatile("cp.async.wait_group 0;" ::: "memory");
        __syncthreads();

        int buf = it & 1;
        const float* a = sA + buf*G_ABUF;
        const float* bsm = sB + buf*G_BBUF;

        #pragma unroll
        for (int kt = 0; kt < 4; kt++) {
            int kk = kt*8 + t4;
            float4 av[2];
            #pragma unroll
            for (int mi = 0; mi < 2; mi++) {
                int r0 = wm*32 + mi*16 + g;
                av[mi].x = a[r0*GAS + kk];
                av[mi].y = a[(r0+8)*GAS + kk];
                av[mi].z = a[r0*GAS + kk + 4];
                av[mi].w = a[(r0+8)*GAS + kk + 4];
            }
            #pragma unroll
            for (int ni = 0; ni < 4; ni++) {
                int n = wn*32 + ni*8 + g;
                float2 bf;
                bf.x = bsm[n*GAS + kk];
                bf.y = bsm[n*GAS + kk + 4];
                mma_tf32(acc[0][ni], av[0], bf);
                mma_tf32(acc[1][ni], av[1], bf);
            }
        }

        if (it + 2 < nIter) {
            __syncthreads();
            int k0 = (it + 2) * 32;
            #pragma unroll
            for (int p = 0; p < 4; p++) {
                int c = tid + p*256;
                int row = c >> 3, off = (c & 7) * 4;
                cpa16(sAu + (unsigned int)((buf*G_ABUF + row*GAS + off)*4),
                      A + (size_t)(ms+row)*K + k0 + off);
            }
            #pragma unroll
            for (int p = 0; p < 2; p++) {
                int c = tid + p*256;
                int row = c >> 3, off = (c & 7) * 4;
                cpa16(sBu + (unsigned int)((buf*G_BBUF + row*GAS + off)*4),
                      Bw + (size_t)(ns+row)*K + k0 + off);
            }
            asm volatile("cp.async.commit_group;" ::: "memory");
        }
    }

    #pragma unroll
    for (int mi = 0; mi < 2; mi++) {
        #pragma unroll
        for (int ni = 0; ni < 4; ni++) {
            int m0 = ms + wm*32 + mi*16 + g;
            int n  = ns + wn*32 + ni*8 + t4*2;
            float b0 = bias[n], b1 = bias[n+1];
            {
                float2 v;
                v.x = fmaxf(acc[mi][ni].x + b0, 0.f);
                v.y = fmaxf(acc[mi][ni].y + b1, 0.f);
                if (Res) { v.x += Res[(size_t)m0*N + n]; v.y += Res[(size_t)m0*N + n + 1]; }
                *(float2*)&C[(size_t)m0*N + n] = v;
            }
            {
                int m1 = m0 + 8;
                float2 v;
                v.x = fmaxf(acc[mi][ni].z + b0, 0.f);
                v.y = fmaxf(acc[mi][ni].w + b1, 0.f);
                if (Res) { v.x += Res[(size_t)m1*N + n]; v.y += Res[(size_t)m1*N + n + 1]; }
                *(float2*)&C[(size_t)m1*N + n] = v;
            }
        }
    }
}

// ---------------- launcher ----------------------------------------------------
extern "C" void kernel_launch(void* const* d_in, const int* in_sizes, int n_in,
                              void* d_out, int out_size)
{
    const float* x     = (const float*)d_in[0];
    const float* ln1g  = (const float*)d_in[1];
    const float* ln1b  = (const float*)d_in[2];
    const float* accw  = (const float*)d_in[3];
    const float* accb  = (const float*)d_in[4];
    const float* accwo = (const float*)d_in[5];
    const float* accbo = (const float*)d_in[6];
    const float* gyrw  = (const float*)d_in[7];
    const float* gyrb  = (const float*)d_in[8];
    const float* gyrwo = (const float*)d_in[9];
    const float* gyrbo = (const float*)d_in[10];
    const float* convw = (const float*)d_in[11];
    const float* ln2g  = (const float*)d_in[12];
    const float* ln2b  = (const float*)d_in[13];
    const float* w1    = (const float*)d_in[14];
    const float* b1    = (const float*)d_in[15];
    const float* w2    = (const float*)d_in[16];
    const float* b2    = (const float*)d_in[17];
    float* out = (float*)d_out;

    cudaFuncSetAttribute(k1b_qkv_mma,     cudaFuncAttributeMaxDynamicSharedMemorySize, K1B_SMEM);
    cudaFuncSetAttribute(k2_attn_mma,     cudaFuncAttributeMaxDynamicSharedMemorySize, K2_SMEM);
    cudaFuncSetAttribute(k3_proj_ln2_mma, cudaFuncAttributeMaxDynamicSharedMemorySize, K3_SMEM);
    cudaFuncSetAttribute(gemm_tf32_v3,    cudaFuncAttributeMaxDynamicSharedMemorySize, G_SMEM);

    void *p_x1, *p_x1n, *p_h;
    cudaGetSymbolAddress(&p_x1,  g_x1);
    cudaGetSymbolAddress(&p_x1n, g_x1n);
    cudaGetSymbolAddress(&p_h,   g_h);

    k1_ln_conv<<<TT/8, 256>>>(x, ln1g, ln1b, convw);
    k1b_qkv_mma<<<TT/64, 256, K1B_SMEM>>>(accw, accb, gyrw, gyrb);
    k2_attn_mma<<<2*BB*NH*2, 256, K2_SMEM>>>();
    k3_proj_ln2_mma<<<TT/64, 256, K3_SMEM>>>(x, accwo, accbo, gyrwo, gyrbo, ln2g, ln2b);

    // MLP: h = relu(x1n @ w1^T + b1);  out = x1 + relu(h @ w2^T + b2)
    gemm_tf32_v3<<<dim3(TT/128, 384/64), 256, G_SMEM>>>(
        (const float*)p_x1n, w1, b1, nullptr, (float*)p_h, 384, 192);
    gemm_tf32_v3<<<dim3(TT/128, 192/64), 256, G_SMEM>>>(
        (const float*)p_h, w2, b2, (const float*)p_x1, out, 192, 384);
}